// round 9
// baseline (speedup 1.0000x reference)
#include <cuda_runtime.h>
#include <math.h>
#include <stdint.h>

#define BB 4
#define TT 2048
#define DD 1024
#define HH 16
#define HD 64
#define SCALE_F 0.125f   // 1/sqrt(64)

// Scratch. g_q, g_k, g_o: [B, H, T, hd] (tf32-rounded values).
// g_v: [B, H, hd, T] (TRANSPOSED, tf32-rounded).
__device__ float g_q[(size_t)BB * HH * TT * HD];
__device__ float g_k[(size_t)BB * HH * TT * HD];
__device__ float g_v[(size_t)BB * HH * TT * HD];
__device__ float g_o[(size_t)BB * HH * TT * HD];
// Pre-rounded X: [B*T, D]
__device__ float g_x[(size_t)BB * TT * DD];
// W^T scratch: 4 matrices [N=1024][K=1024], tf32-rounded
__device__ float g_wt[(size_t)4 * DD * DD];

__device__ __forceinline__ uint32_t f2tf32(float f) {
    uint32_t r;
    asm("cvt.rna.tf32.f32 %0, %1;" : "=r"(r) : "f"(f));
    return r;
}
__device__ __forceinline__ float rtf32(float f) {
    return __uint_as_float(f2tf32(f));
}

__device__ __forceinline__ void mma_tf32(float* d, const uint32_t* a,
                                         const uint32_t* b) {
    asm volatile(
        "mma.sync.aligned.m16n8k8.row.col.f32.tf32.tf32.f32 "
        "{%0,%1,%2,%3}, {%4,%5,%6,%7}, {%8,%9}, {%0,%1,%2,%3};"
        : "+f"(d[0]), "+f"(d[1]), "+f"(d[2]), "+f"(d[3])
        : "r"(a[0]), "r"(a[1]), "r"(a[2]), "r"(a[3]),
          "r"(b[0]), "r"(b[1]));
}

__device__ __forceinline__ void cpasync16(void* sptr, const void* gptr) {
    uint32_t sa = (uint32_t)__cvta_generic_to_shared(sptr);
    asm volatile("cp.async.ca.shared.global [%0], [%1], 16;"
                 :: "r"(sa), "l"(gptr));
}
#define CP_COMMIT() asm volatile("cp.async.commit_group;" ::: "memory")
#define CP_WAIT0()  asm volatile("cp.async.wait_group 0;" ::: "memory")

// XOR swizzle for 64-col fp32 tiles (attention); 16B-granular
#define SW(row, col) (((row) << 6) + ((col) ^ (((row) & 7) << 2)))

// ---------------------------------------------------------------------------
// Pre-round X to tf32
// ---------------------------------------------------------------------------
__global__ __launch_bounds__(256) void round_x(const float* __restrict__ x)
{
    size_t i = ((size_t)blockIdx.x * 256 + threadIdx.x) * 4;
    float4 v = *(const float4*)&x[i];
    uint4 u;
    u.x = f2tf32(v.x); u.y = f2tf32(v.y);
    u.z = f2tf32(v.z); u.w = f2tf32(v.w);
    *(uint4*)&g_x[i] = u;
}

// ---------------------------------------------------------------------------
// Weight transpose: W [K,N] -> g_wt slice [N,K], tf32-rounded
// ---------------------------------------------------------------------------
__global__ __launch_bounds__(256) void transpose_w(
    const float* __restrict__ Wq, const float* __restrict__ Wk,
    const float* __restrict__ Wv, const float* __restrict__ Wo)
{
    const float* src = (blockIdx.z == 0) ? Wq : (blockIdx.z == 1) ? Wk
                     : (blockIdx.z == 2) ? Wv : Wo;
    float* dst = g_wt + (size_t)blockIdx.z * DD * DD;

    __shared__ float tile[32][33];
    int x = blockIdx.x * 32 + threadIdx.x;
    int y0 = blockIdx.y * 32;
#pragma unroll
    for (int j = threadIdx.y; j < 32; j += 8)
        tile[j][threadIdx.x] = src[(size_t)(y0 + j) * DD + x];
    __syncthreads();
    int x2 = y0 + threadIdx.x;
    int y2 = blockIdx.x * 32;
#pragma unroll
    for (int j = threadIdx.y; j < 32; j += 8)
        dst[(size_t)(y2 + j) * DD + x2] = rtf32(tile[threadIdx.x][j]);
}

// ---------------------------------------------------------------------------
// cp.async 2-stage tf32 GEMM, BK=32 (unchanged from round 8)
// ---------------------------------------------------------------------------
#define BK 32
#define ASTRIDE 36
#define TILE_F (128 * ASTRIDE)          // 4608 floats

template <int MODE>
__global__ __launch_bounds__(256) void gemm_tc(
    const float* __restrict__ b0, const float* __restrict__ b1,
    const float* __restrict__ b2, float* __restrict__ OutDirect)
{
    extern __shared__ float smd[];

    int tid = threadIdx.x;
    int wid = tid >> 5;
    int lane = tid & 31;
    int warp_m = wid & 1;
    int warp_n = wid >> 1;
    int r = lane >> 2;
    int c = lane & 3;
    int n0 = blockIdx.x * 128;
    int m0 = blockIdx.y * 128;

    const float* Wt;
    const float* bias;
    float* out;
    const float* Ain;
    int zsel = 0;
    if (MODE == 0) {
        zsel = blockIdx.z;
        Wt = g_wt + (size_t)zsel * DD * DD;
        bias = (zsel == 0) ? b0 : (zsel == 1) ? b1 : b2;
        out = (zsel == 0) ? g_q : (zsel == 1) ? g_k : g_v;
        Ain = g_x;
    } else {
        Wt = g_wt + (size_t)3 * DD * DD;
        bias = b0;
        out = OutDirect;
        Ain = g_o;
    }

    auto load_stage = [&](int st, int kt) {
#pragma unroll
        for (int i = 0; i < 4; i++) {
            int idx = tid + i * 256;
            int row = idx >> 3;
            int c4 = idx & 7;
            const float* srcA;
            if (MODE == 0) {
                srcA = Ain + (size_t)(m0 + row) * DD + kt + c4 * 4;
            } else {
                int m = m0 + row;
                int b = m >> 11;
                int t = m & 2047;
                int h = kt >> 6;
                int d0 = (kt & 63) + c4 * 4;
                srcA = Ain + (((size_t)b * HH + h) * TT + t) * HD + d0;
            }
            cpasync16(&smd[st * TILE_F + row * ASTRIDE + c4 * 4], srcA);
            cpasync16(&smd[2 * TILE_F + st * TILE_F + row * ASTRIDE + c4 * 4],
                      Wt + (size_t)(n0 + row) * DD + kt + c4 * 4);
        }
        CP_COMMIT();
    };

    float acc[4][4][4];
#pragma unroll
    for (int mt = 0; mt < 4; mt++)
#pragma unroll
        for (int nt = 0; nt < 4; nt++)
#pragma unroll
            for (int i = 0; i < 4; i++) acc[mt][nt][i] = 0.f;

    const int NIT = DD / BK;
    load_stage(0, 0);

    for (int it = 0; it < NIT; it++) {
        CP_WAIT0();
        __syncthreads();

        if (it + 1 < NIT)
            load_stage((it + 1) & 1, (it + 1) * BK);

        const float* cA = &smd[(it & 1) * TILE_F];
        const float* cB = &smd[2 * TILE_F + (it & 1) * TILE_F];
#pragma unroll
        for (int ks = 0; ks < 4; ks++) {
            int k0 = ks * 8;
            uint32_t af[4][4], bf[4][2];
#pragma unroll
            for (int mt = 0; mt < 4; mt++) {
                const float* base = &cA[(warp_m * 64 + mt * 16 + r) * ASTRIDE + k0 + c];
                af[mt][0] = __float_as_uint(base[0]);
                af[mt][1] = __float_as_uint(base[8 * ASTRIDE]);
                af[mt][2] = __float_as_uint(base[4]);
                af[mt][3] = __float_as_uint(base[8 * ASTRIDE + 4]);
            }
#pragma unroll
            for (int nt = 0; nt < 4; nt++) {
                const float* base = &cB[(warp_n * 32 + nt * 8 + r) * ASTRIDE + k0 + c];
                bf[nt][0] = __float_as_uint(base[0]);
                bf[nt][1] = __float_as_uint(base[4]);
            }
#pragma unroll
            for (int mt = 0; mt < 4; mt++)
#pragma unroll
                for (int nt = 0; nt < 4; nt++)
                    mma_tf32(acc[mt][nt], af[mt], bf[nt]);
        }
    }

#pragma unroll
    for (int nt = 0; nt < 4; nt++) {
        int col = n0 + warp_n * 32 + nt * 8 + c * 2;
        float bx = __ldg(&bias[col]);
        float by = __ldg(&bias[col + 1]);
#pragma unroll
        for (int mt = 0; mt < 4; mt++) {
            int row0 = m0 + warp_m * 64 + mt * 16 + r;
            float2 v0, v1;
            if (MODE == 0) {
                v0.x = rtf32(acc[mt][nt][0] + bx);
                v0.y = rtf32(acc[mt][nt][1] + by);
                v1.x = rtf32(acc[mt][nt][2] + bx);
                v1.y = rtf32(acc[mt][nt][3] + by);
                int head = col >> 6;
                int d = col & 63;
                int b = row0 >> 11;
                int t = row0 & 2047;
                if (zsel == 2) {
                    size_t vb = ((size_t)b * HH + head) * HD;
                    out[(vb + d) * TT + t] = v0.x;
                    out[(vb + d + 1) * TT + t] = v0.y;
                    out[(vb + d) * TT + t + 8] = v1.x;
                    out[(vb + d + 1) * TT + t + 8] = v1.y;
                } else {
                    size_t base = (((size_t)b * HH + head) * TT + t) * HD + d;
                    *(float2*)&out[base] = v0;
                    *(float2*)&out[base + 8 * HD] = v1;
                }
            } else {
                v0.x = acc[mt][nt][0] + bx;
                v0.y = acc[mt][nt][1] + by;
                v1.x = acc[mt][nt][2] + bx;
                v1.y = acc[mt][nt][3] + by;
                *(float2*)&out[(size_t)row0 * DD + col] = v0;
                *(float2*)&out[(size_t)(row0 + 8) * DD + col] = v1;
            }
        }
    }
}

// ---------------------------------------------------------------------------
// Tensor-core causal flash attention: 256 threads / 8 warps, Q-tile 128,
// ONE 16-row m-frag per warp -> ~96 live floats/thread, no spills, 2 CTAs/SM.
// K/V tiles (64 keys) double-buffered via cp.async; 1 barrier per tile.
// Dynamic smem 96KB: sP 32K | sK[2] 32K | sV[2] 32K.
// ---------------------------------------------------------------------------
__global__ __launch_bounds__(256, 2) void attn_tc()
{
    extern __shared__ float sm[];
    float* sP = sm;                      // 128x64 swizzled

    int bh = blockIdx.y;
    int m0 = blockIdx.x * 128;
    int tid = threadIdx.x;
    int wid = tid >> 5;
    int lane = tid & 31;
    int r = lane >> 2;
    int c = lane & 3;

    const float* Qb  = g_q + (size_t)bh * TT * HD;
    const float* Kb  = g_k + (size_t)bh * TT * HD;
    const float* Vtb = g_v + (size_t)bh * HD * TT;   // [d][T]
    float* Ob        = g_o + (size_t)bh * TT * HD;

    const int NT = blockIdx.x * 2 + 2;

    // ---- K/V tile 0 ----
#pragma unroll
    for (int i = 0; i < 4; i++) {
        int idx = tid + i * 256;          // 0..1023
        int row = idx >> 4;               // 0..63
        int c4 = idx & 15;
        cpasync16(&sm[8192 + SW(row, c4 * 4)],
                  &Kb[(size_t)row * HD + c4 * 4]);
        cpasync16(&sm[16384 + SW(row, c4 * 4)],
                  &Vtb[(size_t)row * TT + c4 * 4]);
    }
    CP_COMMIT();

    // ---- Q tile -> sP ----
#pragma unroll
    for (int i = 0; i < 8; i++) {
        int idx = tid + i * 256;          // 0..2047
        int row = idx >> 4;               // 0..127
        int c4 = idx & 15;
        *(float4*)&sP[SW(row, c4 * 4)] =
            *(const float4*)&Qb[(size_t)(m0 + row) * HD + c4 * 4];
    }
    __syncthreads();

    int lr = wid * 16 + r;                // warp's m-frag rows: lr, lr+8
    uint32_t qf[8][4];
#pragma unroll
    for (int kc = 0; kc < 8; kc++) {
        qf[kc][0] = __float_as_uint(sP[SW(lr,     kc * 8 + c)]);
        qf[kc][1] = __float_as_uint(sP[SW(lr + 8, kc * 8 + c)]);
        qf[kc][2] = __float_as_uint(sP[SW(lr,     kc * 8 + c + 4)]);
        qf[kc][3] = __float_as_uint(sP[SW(lr + 8, kc * 8 + c + 4)]);
    }
    __syncthreads();   // all warps have Q frags before sP becomes P

    float o[8][4];
#pragma unroll
    for (int nt = 0; nt < 8; nt++)
#pragma unroll
        for (int i = 0; i < 4; i++) o[nt][i] = 0.f;

    float mr0 = -INFINITY, mr1 = -INFINITY;
    float l0 = 0.f, l1 = 0.f;
    int rg0 = m0 + lr;
    int rg1 = rg0 + 8;

    for (int s = 0; s < NT; s++) {
        int kt = s * 64;
        CP_WAIT0();
        __syncthreads();          // tile s visible; all warps done with s-1

        if (s + 1 < NT) {
            int kt2 = (s + 1) * 64;
            int st2 = (s + 1) & 1;
#pragma unroll
            for (int i = 0; i < 4; i++) {
                int idx = tid + i * 256;
                int row = idx >> 4;
                int c4 = idx & 15;
                cpasync16(&sm[8192 + st2 * 4096 + SW(row, c4 * 4)],
                          &Kb[(size_t)(kt2 + row) * HD + c4 * 4]);
                cpasync16(&sm[16384 + st2 * 4096 + SW(row, c4 * 4)],
                          &Vtb[(size_t)row * TT + kt2 + c4 * 4]);
            }
            CP_COMMIT();
        }

        const float* sK = sm + 8192 + (s & 1) * 4096;
        const float* sV = sm + 16384 + (s & 1) * 4096;

        // ---- S = Q K^T ----
        float sc[8][4];
#pragma unroll
        for (int nt = 0; nt < 8; nt++)
#pragma unroll
            for (int i = 0; i < 4; i++) sc[nt][i] = 0.f;
#pragma unroll
        for (int kc = 0; kc < 8; kc++) {
#pragma unroll
            for (int nt = 0; nt < 8; nt++) {
                uint32_t bf[2];
                bf[0] = __float_as_uint(sK[SW(nt * 8 + r, kc * 8 + c)]);
                bf[1] = __float_as_uint(sK[SW(nt * 8 + r, kc * 8 + c + 4)]);
                mma_tf32(sc[nt], qf[kc], bf);
            }
        }

        // ---- scale, mask, online softmax ----
        bool need_mask = (kt + 63 > m0);
        float mx0 = mr0, mx1 = mr1;
#pragma unroll
        for (int nt = 0; nt < 8; nt++) {
            float* sv = sc[nt];
            sv[0] *= SCALE_F; sv[1] *= SCALE_F;
            sv[2] *= SCALE_F; sv[3] *= SCALE_F;
            if (need_mask) {
                int col0 = kt + nt * 8 + 2 * c;
                if (col0     > rg0) sv[0] = -INFINITY;
                if (col0 + 1 > rg0) sv[1] = -INFINITY;
                if (col0     > rg1) sv[2] = -INFINITY;
                if (col0 + 1 > rg1) sv[3] = -INFINITY;
            }
            mx0 = fmaxf(mx0, fmaxf(sv[0], sv[1]));
            mx1 = fmaxf(mx1, fmaxf(sv[2], sv[3]));
        }
        mx0 = fmaxf(mx0, __shfl_xor_sync(0xffffffffu, mx0, 1));
        mx0 = fmaxf(mx0, __shfl_xor_sync(0xffffffffu, mx0, 2));
        mx1 = fmaxf(mx1, __shfl_xor_sync(0xffffffffu, mx1, 1));
        mx1 = fmaxf(mx1, __shfl_xor_sync(0xffffffffu, mx1, 2));

        float a0 = __expf(mr0 - mx0);     // exp(-inf)=0 handles first tile
        float a1 = __expf(mr1 - mx1);
        float sum0 = 0.f, sum1 = 0.f;
        __syncwarp();
#pragma unroll
        for (int nt = 0; nt < 8; nt++) {
            float p0 = rtf32(__expf(sc[nt][0] - mx0));
            float p1 = rtf32(__expf(sc[nt][1] - mx0));
            float p2 = rtf32(__expf(sc[nt][2] - mx1));
            float p3 = rtf32(__expf(sc[nt][3] - mx1));
            sum0 += p0 + p1;
            sum1 += p2 + p3;
            *(float2*)&sP[SW(lr,     nt * 8 + 2 * c)] = make_float2(p0, p1);
            *(float2*)&sP[SW(lr + 8, nt * 8 + 2 * c)] = make_float2(p2, p3);
        }
        sum0 += __shfl_xor_sync(0xffffffffu, sum0, 1);
        sum0 += __shfl_xor_sync(0xffffffffu, sum0, 2);
        sum1 += __shfl_xor_sync(0xffffffffu, sum1, 1);
        sum1 += __shfl_xor_sync(0xffffffffu, sum1, 2);
        l0 = l0 * a0 + sum0;
        l1 = l1 * a1 + sum1;
#pragma unroll
        for (int nt = 0; nt < 8; nt++) {
            o[nt][0] *= a0; o[nt][1] *= a0;
            o[nt][2] *= a1; o[nt][3] *= a1;
        }
        mr0 = mx0; mr1 = mx1;
        __syncwarp();

        // ---- O += P V (P read back from own 16-row band) ----
#pragma unroll
        for (int kc = 0; kc < 8; kc++) {
            uint32_t af[4];
            af[0] = __float_as_uint(sP[SW(lr,     kc * 8 + c)]);
            af[1] = __float_as_uint(sP[SW(lr + 8, kc * 8 + c)]);
            af[2] = __float_as_uint(sP[SW(lr,     kc * 8 + c + 4)]);
            af[3] = __float_as_uint(sP[SW(lr + 8, kc * 8 + c + 4)]);
#pragma unroll
            for (int nt = 0; nt < 8; nt++) {
                uint32_t bf[2];
                bf[0] = __float_as_uint(sV[SW(nt * 8 + r, kc * 8 + c)]);
                bf[1] = __float_as_uint(sV[SW(nt * 8 + r, kc * 8 + c + 4)]);
                mma_tf32(o[nt], af, bf);
            }
        }
    }

    // ---- output (tf32-rounded; feeds MODE 1 GEMM) ----
    float i0 = 1.f / l0, i1 = 1.f / l1;
#pragma unroll
    for (int nt = 0; nt < 8; nt++) {
        *(float2*)&Ob[(size_t)rg0 * HD + nt * 8 + 2 * c] =
            make_float2(rtf32(o[nt][0] * i0), rtf32(o[nt][1] * i0));
        *(float2*)&Ob[(size_t)rg1 * HD + nt * 8 + 2 * c] =
            make_float2(rtf32(o[nt][2] * i1), rtf32(o[nt][3] * i1));
    }
}

extern "C" void kernel_launch(void* const* d_in, const int* in_sizes, int n_in,
                              void* d_out, int out_size)
{
    const float* x  = (const float*)d_in[0];
    const float* Wq = (const float*)d_in[1];
    const float* bq = (const float*)d_in[2];
    const float* Wk = (const float*)d_in[3];
    const float* bk = (const float*)d_in[4];
    const float* Wv = (const float*)d_in[5];
    const float* bv = (const float*)d_in[6];
    const float* Wo = (const float*)d_in[7];
    const float* bo = (const float*)d_in[8];
    float* out = (float*)d_out;

    const int GEMM_SMEM = 4 * TILE_F * 4;   // 73728 B
    cudaFuncSetAttribute(gemm_tc<0>, cudaFuncAttributeMaxDynamicSharedMemorySize,
                         GEMM_SMEM);
    cudaFuncSetAttribute(gemm_tc<1>, cudaFuncAttributeMaxDynamicSharedMemorySize,
                         GEMM_SMEM);
    cudaFuncSetAttribute(attn_tc, cudaFuncAttributeMaxDynamicSharedMemorySize,
                         96 * 1024);

    round_x<<<(BB * TT * DD) / (256 * 4), 256>>>(x);

    dim3 gt(32, 32, 4);
    transpose_w<<<gt, dim3(32, 8)>>>(Wq, Wk, Wv, Wo);

    dim3 g1(DD / 128, (BB * TT) / 128, 3);
    gemm_tc<0><<<g1, 256, GEMM_SMEM>>>(bq, bk, bv, nullptr);

    dim3 g2(TT / 128, BB * HH);
    attn_tc<<<g2, 256, 96 * 1024>>>();

    dim3 g3(DD / 128, (BB * TT) / 128);
    gemm_tc<1><<<g3, 256, GEMM_SMEM>>>(bo, nullptr, nullptr, out);
}

// round 10
// speedup vs baseline: 1.9603x; 1.9603x over previous
#include <cuda_runtime.h>
#include <cuda_fp16.h>
#include <math.h>
#include <stdint.h>

#define BB 4
#define TT 2048
#define DD 1024
#define HH 16
#define HD 64
#define SCALE_F 0.125f   // 1/sqrt(64)

// fp16 scratch. g_qh, g_kh, g_oh: [B, H, T, hd]. g_vth: [B, H, hd, T].
__device__ __half g_qh[(size_t)BB * HH * TT * HD];
__device__ __half g_kh[(size_t)BB * HH * TT * HD];
__device__ __half g_vth[(size_t)BB * HH * TT * HD];
__device__ __half g_oh[(size_t)BB * HH * TT * HD];
__device__ __half g_xh[(size_t)BB * TT * DD];          // fp16 X
__device__ __half g_wth[(size_t)4 * DD * DD];          // W^T [N][K] fp16

__device__ __forceinline__ void mma_f16(float* d, const uint32_t* a,
                                        const uint32_t* b) {
    asm volatile(
        "mma.sync.aligned.m16n8k16.row.col.f32.f16.f16.f32 "
        "{%0,%1,%2,%3}, {%4,%5,%6,%7}, {%8,%9}, {%0,%1,%2,%3};"
        : "+f"(d[0]), "+f"(d[1]), "+f"(d[2]), "+f"(d[3])
        : "r"(a[0]), "r"(a[1]), "r"(a[2]), "r"(a[3]),
          "r"(b[0]), "r"(b[1]));
}

__device__ __forceinline__ void cpasync16(void* sptr, const void* gptr) {
    uint32_t sa = (uint32_t)__cvta_generic_to_shared(sptr);
    asm volatile("cp.async.ca.shared.global [%0], [%1], 16;"
                 :: "r"(sa), "l"(gptr));
}
#define CP_COMMIT() asm volatile("cp.async.commit_group;" ::: "memory")
#define CP_WAIT0()  asm volatile("cp.async.wait_group 0;" ::: "memory")

// ---------------------------------------------------------------------------
// X -> fp16
// ---------------------------------------------------------------------------
__global__ __launch_bounds__(256) void round_x(const float* __restrict__ x)
{
    size_t i = ((size_t)blockIdx.x * 256 + threadIdx.x) * 4;
    float4 v = *(const float4*)&x[i];
    __half2 h0 = __floats2half2_rn(v.x, v.y);
    __half2 h1 = __floats2half2_rn(v.z, v.w);
    *(uint2*)&g_xh[i] = make_uint2(*(uint32_t*)&h0, *(uint32_t*)&h1);
}

// ---------------------------------------------------------------------------
// Weight transpose: W [K,N] f32 -> g_wth slice [N,K] fp16
// ---------------------------------------------------------------------------
__global__ __launch_bounds__(256) void transpose_w(
    const float* __restrict__ Wq, const float* __restrict__ Wk,
    const float* __restrict__ Wv, const float* __restrict__ Wo)
{
    const float* src = (blockIdx.z == 0) ? Wq : (blockIdx.z == 1) ? Wk
                     : (blockIdx.z == 2) ? Wv : Wo;
    __half* dst = g_wth + (size_t)blockIdx.z * DD * DD;

    __shared__ float tile[32][33];
    int x = blockIdx.x * 32 + threadIdx.x;
    int y0 = blockIdx.y * 32;
#pragma unroll
    for (int j = threadIdx.y; j < 32; j += 8)
        tile[j][threadIdx.x] = src[(size_t)(y0 + j) * DD + x];
    __syncthreads();
    int x2 = y0 + threadIdx.x;
    int y2 = blockIdx.x * 32;
#pragma unroll
    for (int j = threadIdx.y; j < 32; j += 8)
        dst[(size_t)(y2 + j) * DD + x2] = __float2half_rn(tile[threadIdx.x][j]);
}

// ---------------------------------------------------------------------------
// fp16 cp.async 2-stage GEMM, BK=64: C[128x128] = A @ Wt^T + b
// MODE 0: A = g_xh; z=0 -> g_qh, z=1 -> g_kh, z=2 -> g_vth (transposed);
//         outputs stored as fp16.
// MODE 1: A = g_oh (gathered), out = d_out f32 [B*T, D].
// 256 threads, 8 warps (2m x 4n), warp tile 64x32.
// Smem: half rows of 72 (64 data + 8 pad); 4 tiles x 9216 halves = 72 KB.
// ---------------------------------------------------------------------------
#define BKH 64
#define HSTR 72
#define TILE_H (128 * HSTR)     // 9216 halves

template <int MODE>
__global__ __launch_bounds__(256) void gemm_tc(
    const float* __restrict__ b0, const float* __restrict__ b1,
    const float* __restrict__ b2, float* __restrict__ OutDirect)
{
    extern __shared__ __half smh[];
    // A st0 | A st1 | B st0 | B st1

    int tid = threadIdx.x;
    int wid = tid >> 5;
    int lane = tid & 31;
    int warp_m = wid & 1;
    int warp_n = wid >> 1;
    int r = lane >> 2;
    int c = lane & 3;
    int n0 = blockIdx.x * 128;
    int m0 = blockIdx.y * 128;

    const __half* Wt;
    const float* bias;
    const __half* Ain;
    int zsel = 0;
    if (MODE == 0) {
        zsel = blockIdx.z;
        Wt = g_wth + (size_t)zsel * DD * DD;
        bias = (zsel == 0) ? b0 : (zsel == 1) ? b1 : b2;
        Ain = g_xh;
    } else {
        Wt = g_wth + (size_t)3 * DD * DD;
        bias = b0;
        Ain = g_oh;
    }

    auto load_stage = [&](int st, int kt) {
#pragma unroll
        for (int i = 0; i < 4; i++) {
            int idx = tid + i * 256;        // 0..1023
            int row = idx >> 3;             // 0..127
            int ch = idx & 7;               // 16B chunk (8 halves)
            const __half* srcA;
            if (MODE == 0) {
                srcA = Ain + (size_t)(m0 + row) * DD + kt + ch * 8;
            } else {
                int m = m0 + row;
                int b = m >> 11;
                int t = m & 2047;
                int h = kt >> 6;            // BK==HD: one head per k-tile
                srcA = Ain + (((size_t)b * HH + h) * TT + t) * HD + ch * 8;
            }
            cpasync16(&smh[st * TILE_H + row * HSTR + ch * 8], srcA);
            cpasync16(&smh[2 * TILE_H + st * TILE_H + row * HSTR + ch * 8],
                      Wt + (size_t)(n0 + row) * DD + kt + ch * 8);
        }
        CP_COMMIT();
    };

    float acc[4][4][4];
#pragma unroll
    for (int mt = 0; mt < 4; mt++)
#pragma unroll
        for (int nt = 0; nt < 4; nt++)
#pragma unroll
            for (int i = 0; i < 4; i++) acc[mt][nt][i] = 0.f;

    const int NIT = DD / BKH;   // 16
    load_stage(0, 0);

    for (int it = 0; it < NIT; it++) {
        CP_WAIT0();
        __syncthreads();

        if (it + 1 < NIT)
            load_stage((it + 1) & 1, (it + 1) * BKH);

        const __half* cA = &smh[(it & 1) * TILE_H];
        const __half* cB = &smh[2 * TILE_H + (it & 1) * TILE_H];
#pragma unroll
        for (int ks = 0; ks < 4; ks++) {
            int k0 = ks * 16;
            uint32_t af[4][4], bf[4][2];
#pragma unroll
            for (int mt = 0; mt < 4; mt++) {
                const __half* base = &cA[(warp_m * 64 + mt * 16 + r) * HSTR + k0 + 2 * c];
                af[mt][0] = *(const uint32_t*)base;
                af[mt][1] = *(const uint32_t*)(base + 8 * HSTR);
                af[mt][2] = *(const uint32_t*)(base + 8);
                af[mt][3] = *(const uint32_t*)(base + 8 * HSTR + 8);
            }
#pragma unroll
            for (int nt = 0; nt < 4; nt++) {
                const __half* base = &cB[(warp_n * 32 + nt * 8 + r) * HSTR + k0 + 2 * c];
                bf[nt][0] = *(const uint32_t*)base;
                bf[nt][1] = *(const uint32_t*)(base + 8);
            }
#pragma unroll
            for (int mt = 0; mt < 4; mt++)
#pragma unroll
                for (int nt = 0; nt < 4; nt++)
                    mma_f16(acc[mt][nt], af[mt], bf[nt]);
        }
    }

#pragma unroll
    for (int nt = 0; nt < 4; nt++) {
        int col = n0 + warp_n * 32 + nt * 8 + c * 2;
        float bx = __ldg(&bias[col]);
        float by = __ldg(&bias[col + 1]);
#pragma unroll
        for (int mt = 0; mt < 4; mt++) {
            int row0 = m0 + warp_m * 64 + mt * 16 + r;
            if (MODE == 0) {
                __half2 h0 = __floats2half2_rn(acc[mt][nt][0] + bx,
                                               acc[mt][nt][1] + by);
                __half2 h1 = __floats2half2_rn(acc[mt][nt][2] + bx,
                                               acc[mt][nt][3] + by);
                int head = col >> 6;
                int d = col & 63;
                int b = row0 >> 11;
                int t = row0 & 2047;
                if (zsel == 2) {
                    __half* vt = g_vth + (((size_t)b * HH + head) * HD) * TT;
                    vt[(size_t)d * TT + t]           = __low2half(h0);
                    vt[(size_t)(d + 1) * TT + t]     = __high2half(h0);
                    vt[(size_t)d * TT + t + 8]       = __low2half(h1);
                    vt[(size_t)(d + 1) * TT + t + 8] = __high2half(h1);
                } else {
                    __half* out = (zsel == 0) ? g_qh : g_kh;
                    size_t base = (((size_t)b * HH + head) * TT + t) * HD + d;
                    *(__half2*)&out[base] = h0;
                    *(__half2*)&out[base + 8 * HD] = h1;
                }
            } else {
                float2 v0, v1;
                v0.x = acc[mt][nt][0] + bx;
                v0.y = acc[mt][nt][1] + by;
                v1.x = acc[mt][nt][2] + bx;
                v1.y = acc[mt][nt][3] + by;
                *(float2*)&OutDirect[(size_t)row0 * DD + col] = v0;
                *(float2*)&OutDirect[(size_t)(row0 + 8) * DD + col] = v1;
            }
        }
    }
}

// ---------------------------------------------------------------------------
// fp16 tensor-core causal flash attention.
// 256 threads / 8 warps, Q-tile 128, one 16-row m-frag per warp.
// P stays in REGISTERS (C-frag -> A-frag is a pure half2 pack for k16).
// K/V 64-key tiles double-buffered via cp.async.
// Smem 55296B: sQ 128x72h | sK[2] 64x72h | sV[2] 64x72h.
// ---------------------------------------------------------------------------
__global__ __launch_bounds__(256, 2) void attn_fa()
{
    extern __shared__ __half sa[];
    // sQ at 0 (9216h), sK at 9216 (+4608/stage), sV at 18432 (+4608/stage)

    int bh = blockIdx.y;
    int m0 = blockIdx.x * 128;
    int tid = threadIdx.x;
    int wid = tid >> 5;
    int lane = tid & 31;
    int r = lane >> 2;
    int c = lane & 3;

    const __half* Qb  = g_qh + (size_t)bh * TT * HD;
    const __half* Kb  = g_kh + (size_t)bh * TT * HD;
    const __half* Vtb = g_vth + (size_t)bh * HD * TT;  // [d][T]
    __half* Ob        = g_oh + (size_t)bh * TT * HD;

    const int NT = blockIdx.x * 2 + 2;

    // K/V tile 0 (64 rows x 64 halves = 512 chunks)
#pragma unroll
    for (int i = 0; i < 2; i++) {
        int idx = tid + i * 256;
        int row = idx >> 3;
        int ch = idx & 7;
        cpasync16(&sa[9216 + row * HSTR + ch * 8],
                  Kb + (size_t)row * HD + ch * 8);
        cpasync16(&sa[18432 + row * HSTR + ch * 8],
                  Vtb + (size_t)row * TT + ch * 8);
    }
    CP_COMMIT();

    // Q tile -> smem (plain 16B copies)
#pragma unroll
    for (int i = 0; i < 4; i++) {
        int idx = tid + i * 256;
        int row = idx >> 3;
        int ch = idx & 7;
        *(uint4*)&sa[row * HSTR + ch * 8] =
            *(const uint4*)&Qb[(size_t)(m0 + row) * HD + ch * 8];
    }
    __syncthreads();

    int lr = wid * 16 + r;
    uint32_t qf[4][4];
#pragma unroll
    for (int kc = 0; kc < 4; kc++) {
        const __half* base = &sa[lr * HSTR + kc * 16 + 2 * c];
        qf[kc][0] = *(const uint32_t*)base;
        qf[kc][1] = *(const uint32_t*)(base + 8 * HSTR);
        qf[kc][2] = *(const uint32_t*)(base + 8);
        qf[kc][3] = *(const uint32_t*)(base + 8 * HSTR + 8);
    }

    float o[8][4];
#pragma unroll
    for (int nt = 0; nt < 8; nt++)
#pragma unroll
        for (int i = 0; i < 4; i++) o[nt][i] = 0.f;

    float mr0 = -INFINITY, mr1 = -INFINITY;
    float l0 = 0.f, l1 = 0.f;
    int rg0 = m0 + lr;
    int rg1 = rg0 + 8;

    for (int s = 0; s < NT; s++) {
        int kt = s * 64;
        CP_WAIT0();
        __syncthreads();

        if (s + 1 < NT) {
            int kt2 = (s + 1) * 64;
            int st2 = (s + 1) & 1;
#pragma unroll
            for (int i = 0; i < 2; i++) {
                int idx = tid + i * 256;
                int row = idx >> 3;
                int ch = idx & 7;
                cpasync16(&sa[9216 + st2 * 4608 + row * HSTR + ch * 8],
                          Kb + (size_t)(kt2 + row) * HD + ch * 8);
                cpasync16(&sa[18432 + st2 * 4608 + row * HSTR + ch * 8],
                          Vtb + (size_t)row * TT + kt2 + ch * 8);
            }
            CP_COMMIT();
        }

        const __half* sK = sa + 9216 + (s & 1) * 4608;
        const __half* sV = sa + 18432 + (s & 1) * 4608;

        // ---- S = Q K^T ----
        float sc[8][4];
#pragma unroll
        for (int nt = 0; nt < 8; nt++)
#pragma unroll
            for (int i = 0; i < 4; i++) sc[nt][i] = 0.f;
#pragma unroll
        for (int kc = 0; kc < 4; kc++) {
#pragma unroll
            for (int nt = 0; nt < 8; nt++) {
                const __half* base = &sK[(nt * 8 + r) * HSTR + kc * 16 + 2 * c];
                uint32_t bf[2];
                bf[0] = *(const uint32_t*)base;
                bf[1] = *(const uint32_t*)(base + 8);
                mma_f16(sc[nt], qf[kc], bf);
            }
        }

        // ---- scale, mask, online softmax; P packed to half2 in regs ----
        bool need_mask = (kt + 63 > m0);
        float mx0 = mr0, mx1 = mr1;
#pragma unroll
        for (int nt = 0; nt < 8; nt++) {
            float* sv = sc[nt];
            sv[0] *= SCALE_F; sv[1] *= SCALE_F;
            sv[2] *= SCALE_F; sv[3] *= SCALE_F;
            if (need_mask) {
                int col0 = kt + nt * 8 + 2 * c;
                if (col0     > rg0) sv[0] = -INFINITY;
                if (col0 + 1 > rg0) sv[1] = -INFINITY;
                if (col0     > rg1) sv[2] = -INFINITY;
                if (col0 + 1 > rg1) sv[3] = -INFINITY;
            }
            mx0 = fmaxf(mx0, fmaxf(sv[0], sv[1]));
            mx1 = fmaxf(mx1, fmaxf(sv[2], sv[3]));
        }
        mx0 = fmaxf(mx0, __shfl_xor_sync(0xffffffffu, mx0, 1));
        mx0 = fmaxf(mx0, __shfl_xor_sync(0xffffffffu, mx0, 2));
        mx1 = fmaxf(mx1, __shfl_xor_sync(0xffffffffu, mx1, 1));
        mx1 = fmaxf(mx1, __shfl_xor_sync(0xffffffffu, mx1, 2));

        float a0 = __expf(mr0 - mx0);
        float a1 = __expf(mr1 - mx1);
        float sum0 = 0.f, sum1 = 0.f;
        uint32_t pk[8][2];
#pragma unroll
        for (int nt = 0; nt < 8; nt++) {
            __half2 h01 = __floats2half2_rn(__expf(sc[nt][0] - mx0),
                                            __expf(sc[nt][1] - mx0));
            __half2 h23 = __floats2half2_rn(__expf(sc[nt][2] - mx1),
                                            __expf(sc[nt][3] - mx1));
            pk[nt][0] = *(uint32_t*)&h01;
            pk[nt][1] = *(uint32_t*)&h23;
            float2 f01 = __half22float2(h01);
            float2 f23 = __half22float2(h23);
            sum0 += f01.x + f01.y;
            sum1 += f23.x + f23.y;
        }
        sum0 += __shfl_xor_sync(0xffffffffu, sum0, 1);
        sum0 += __shfl_xor_sync(0xffffffffu, sum0, 2);
        sum1 += __shfl_xor_sync(0xffffffffu, sum1, 1);
        sum1 += __shfl_xor_sync(0xffffffffu, sum1, 2);
        l0 = l0 * a0 + sum0;
        l1 = l1 * a1 + sum1;
#pragma unroll
        for (int nt = 0; nt < 8; nt++) {
            o[nt][0] *= a0; o[nt][1] *= a0;
            o[nt][2] *= a1; o[nt][3] *= a1;
        }
        mr0 = mx0; mr1 = mx1;

        // ---- O += P V  (P A-frags straight from pk registers) ----
#pragma unroll
        for (int kc = 0; kc < 4; kc++) {
            uint32_t af[4];
            af[0] = pk[2 * kc][0];
            af[1] = pk[2 * kc][1];
            af[2] = pk[2 * kc + 1][0];
            af[3] = pk[2 * kc + 1][1];
#pragma unroll
            for (int nt = 0; nt < 8; nt++) {
                const __half* base = &sV[(nt * 8 + r) * HSTR + kc * 16 + 2 * c];
                uint32_t bf[2];
                bf[0] = *(const uint32_t*)base;
                bf[1] = *(const uint32_t*)(base + 8);
                mma_f16(o[nt], af, bf);
            }
        }
    }

    // ---- output as fp16 (feeds MODE 1 GEMM) ----
    float i0 = 1.f / l0, i1 = 1.f / l1;
#pragma unroll
    for (int nt = 0; nt < 8; nt++) {
        *(__half2*)&Ob[(size_t)rg0 * HD + nt * 8 + 2 * c] =
            __floats2half2_rn(o[nt][0] * i0, o[nt][1] * i0);
        *(__half2*)&Ob[(size_t)rg1 * HD + nt * 8 + 2 * c] =
            __floats2half2_rn(o[nt][2] * i1, o[nt][3] * i1);
    }
}

extern "C" void kernel_launch(void* const* d_in, const int* in_sizes, int n_in,
                              void* d_out, int out_size)
{
    const float* x  = (const float*)d_in[0];
    const float* Wq = (const float*)d_in[1];
    const float* bq = (const float*)d_in[2];
    const float* Wk = (const float*)d_in[3];
    const float* bk = (const float*)d_in[4];
    const float* Wv = (const float*)d_in[5];
    const float* bv = (const float*)d_in[6];
    const float* Wo = (const float*)d_in[7];
    const float* bo = (const float*)d_in[8];
    float* out = (float*)d_out;

    const int GEMM_SMEM = 4 * TILE_H * 2;   // 73728 B
    const int ATTN_SMEM = 27648 * 2;        // 55296 B
    cudaFuncSetAttribute(gemm_tc<0>, cudaFuncAttributeMaxDynamicSharedMemorySize,
                         GEMM_SMEM);
    cudaFuncSetAttribute(gemm_tc<1>, cudaFuncAttributeMaxDynamicSharedMemorySize,
                         GEMM_SMEM);
    cudaFuncSetAttribute(attn_fa, cudaFuncAttributeMaxDynamicSharedMemorySize,
                         ATTN_SMEM);

    round_x<<<(BB * TT * DD) / (256 * 4), 256>>>(x);

    dim3 gt(32, 32, 4);
    transpose_w<<<gt, dim3(32, 8)>>>(Wq, Wk, Wv, Wo);

    dim3 g1(DD / 128, (BB * TT) / 128, 3);
    gemm_tc<0><<<g1, 256, GEMM_SMEM>>>(bq, bk, bv, nullptr);

    dim3 g2(TT / 128, BB * HH);
    attn_fa<<<g2, 256, ATTN_SMEM>>>();

    dim3 g3(DD / 128, (BB * TT) / 128);
    gemm_tc<1><<<g3, 256, GEMM_SMEM>>>(bo, nullptr, nullptr, out);
}

// round 12
// speedup vs baseline: 2.1387x; 1.0910x over previous
#include <cuda_runtime.h>
#include <cuda_fp16.h>
#include <math.h>
#include <stdint.h>

#define BB 4
#define TT 2048
#define DD 1024
#define HH 16
#define HD 64
#define SCALE_F 0.125f   // 1/sqrt(64)

// fp16 scratch. g_qh, g_kh, g_oh: [B, H, T, hd]. g_vth: [B, H, hd, T].
__device__ __half g_qh[(size_t)BB * HH * TT * HD];
__device__ __half g_kh[(size_t)BB * HH * TT * HD];
__device__ __half g_vth[(size_t)BB * HH * TT * HD];
__device__ __half g_oh[(size_t)BB * HH * TT * HD];
__device__ __half g_xh[(size_t)BB * TT * DD];          // fp16 X
__device__ __half g_wth[(size_t)4 * DD * DD];          // W^T [N][K] fp16

__device__ __forceinline__ void mma_f16(float* d, const uint32_t* a,
                                        const uint32_t* b) {
    asm volatile(
        "mma.sync.aligned.m16n8k16.row.col.f32.f16.f16.f32 "
        "{%0,%1,%2,%3}, {%4,%5,%6,%7}, {%8,%9}, {%0,%1,%2,%3};"
        : "+f"(d[0]), "+f"(d[1]), "+f"(d[2]), "+f"(d[3])
        : "r"(a[0]), "r"(a[1]), "r"(a[2]), "r"(a[3]),
          "r"(b[0]), "r"(b[1]));
}

__device__ __forceinline__ void ldsm_x4(uint32_t* d, uint32_t saddr) {
    asm volatile(
        "ldmatrix.sync.aligned.m8n8.x4.shared.b16 {%0,%1,%2,%3}, [%4];"
        : "=r"(d[0]), "=r"(d[1]), "=r"(d[2]), "=r"(d[3]) : "r"(saddr));
}

__device__ __forceinline__ void cpasync16(void* sptr, const void* gptr) {
    uint32_t sa = (uint32_t)__cvta_generic_to_shared(sptr);
    asm volatile("cp.async.ca.shared.global [%0], [%1], 16;"
                 :: "r"(sa), "l"(gptr));
}
#define CP_COMMIT() asm volatile("cp.async.commit_group;" ::: "memory")
#define CP_WAIT0()  asm volatile("cp.async.wait_group 0;" ::: "memory")

// ---------------------------------------------------------------------------
// X -> fp16
// ---------------------------------------------------------------------------
__global__ __launch_bounds__(256) void round_x(const float* __restrict__ x)
{
    size_t i = ((size_t)blockIdx.x * 256 + threadIdx.x) * 4;
    float4 v = *(const float4*)&x[i];
    __half2 h0 = __floats2half2_rn(v.x, v.y);
    __half2 h1 = __floats2half2_rn(v.z, v.w);
    *(uint2*)&g_xh[i] = make_uint2(*(uint32_t*)&h0, *(uint32_t*)&h1);
}

// ---------------------------------------------------------------------------
// Weight transpose: W [K,N] f32 -> g_wth slice [N,K] fp16
// ---------------------------------------------------------------------------
__global__ __launch_bounds__(256) void transpose_w(
    const float* __restrict__ Wq, const float* __restrict__ Wk,
    const float* __restrict__ Wv, const float* __restrict__ Wo)
{
    const float* src = (blockIdx.z == 0) ? Wq : (blockIdx.z == 1) ? Wk
                     : (blockIdx.z == 2) ? Wv : Wo;
    __half* dst = g_wth + (size_t)blockIdx.z * DD * DD;

    __shared__ float tile[32][33];
    int x = blockIdx.x * 32 + threadIdx.x;
    int y0 = blockIdx.y * 32;
#pragma unroll
    for (int j = threadIdx.y; j < 32; j += 8)
        tile[j][threadIdx.x] = src[(size_t)(y0 + j) * DD + x];
    __syncthreads();
    int x2 = y0 + threadIdx.x;
    int y2 = blockIdx.x * 32;
#pragma unroll
    for (int j = threadIdx.y; j < 32; j += 8)
        dst[(size_t)(y2 + j) * DD + x2] = __float2half_rn(tile[threadIdx.x][j]);
}

// ---------------------------------------------------------------------------
// fp16 cp.async 2-stage GEMM, BK=64, ldmatrix fragment loads.
// MODE 0: A = g_xh; z=0 -> g_qh, z=1 -> g_kh, z=2 -> g_vth (transposed).
// MODE 1: A = g_oh (gathered), out = d_out f32 [B*T, D].
// 256 threads, 8 warps (2m x 4n), warp tile 64x32.
// ---------------------------------------------------------------------------
#define BKH 64
#define HSTR 72
#define TILE_H (128 * HSTR)     // 9216 halves

template <int MODE>
__global__ __launch_bounds__(256) void gemm_tc(
    const float* __restrict__ b0, const float* __restrict__ b1,
    const float* __restrict__ b2, float* __restrict__ OutDirect)
{
    extern __shared__ __half smh[];
    // A st0 | A st1 | B st0 | B st1

    int tid = threadIdx.x;
    int wid = tid >> 5;
    int lane = tid & 31;
    int warp_m = wid & 1;
    int warp_n = wid >> 1;
    int r = lane >> 2;
    int c = lane & 3;
    int sub = lane >> 3;          // ldmatrix address group
    int rin = lane & 7;
    int n0 = blockIdx.x * 128;
    int m0 = blockIdx.y * 128;

    uint32_t sbase = (uint32_t)__cvta_generic_to_shared(smh);

    const __half* Wt;
    const float* bias;
    const __half* Ain;
    int zsel = 0;
    if (MODE == 0) {
        zsel = blockIdx.z;
        Wt = g_wth + (size_t)zsel * DD * DD;
        bias = (zsel == 0) ? b0 : (zsel == 1) ? b1 : b2;
        Ain = g_xh;
    } else {
        Wt = g_wth + (size_t)3 * DD * DD;
        bias = b0;
        Ain = g_oh;
    }

    auto load_stage = [&](int st, int kt) {
#pragma unroll
        for (int i = 0; i < 4; i++) {
            int idx = tid + i * 256;
            int row = idx >> 3;
            int ch = idx & 7;
            const __half* srcA;
            if (MODE == 0) {
                srcA = Ain + (size_t)(m0 + row) * DD + kt + ch * 8;
            } else {
                int m = m0 + row;
                int b = m >> 11;
                int t = m & 2047;
                int h = kt >> 6;
                srcA = Ain + (((size_t)b * HH + h) * TT + t) * HD + ch * 8;
            }
            cpasync16(&smh[st * TILE_H + row * HSTR + ch * 8], srcA);
            cpasync16(&smh[2 * TILE_H + st * TILE_H + row * HSTR + ch * 8],
                      Wt + (size_t)(n0 + row) * DD + kt + ch * 8);
        }
        CP_COMMIT();
    };

    // per-thread ldmatrix offsets (in halves, relative to tile base)
    int a_off = (warp_m * 64 + (sub & 1) * 8 + rin) * HSTR + (sub >> 1) * 8;
    int b_off[2];
#pragma unroll
    for (int j = 0; j < 2; j++)
        b_off[j] = (warp_n * 32 + (2 * j + (sub >> 1)) * 8 + rin) * HSTR
                 + (sub & 1) * 8;

    float acc[4][4][4];
#pragma unroll
    for (int mt = 0; mt < 4; mt++)
#pragma unroll
        for (int nt = 0; nt < 4; nt++)
#pragma unroll
            for (int i = 0; i < 4; i++) acc[mt][nt][i] = 0.f;

    const int NIT = DD / BKH;   // 16
    load_stage(0, 0);

    for (int it = 0; it < NIT; it++) {
        CP_WAIT0();
        __syncthreads();

        if (it + 1 < NIT)
            load_stage((it + 1) & 1, (it + 1) * BKH);

        uint32_t aB = sbase + ((it & 1) * TILE_H) * 2;
        uint32_t bB = sbase + (2 * TILE_H + (it & 1) * TILE_H) * 2;
#pragma unroll
        for (int ks = 0; ks < 4; ks++) {
            int k0 = ks * 16;
            uint32_t af[4][4], bf[4][2];
#pragma unroll
            for (int mt = 0; mt < 4; mt++)
                ldsm_x4(af[mt], aB + (a_off + mt * 16 * HSTR + k0) * 2);
#pragma unroll
            for (int j = 0; j < 2; j++) {
                uint32_t t4[4];
                ldsm_x4(t4, bB + (b_off[j] + k0) * 2);
                bf[2 * j][0] = t4[0]; bf[2 * j][1] = t4[1];
                bf[2 * j + 1][0] = t4[2]; bf[2 * j + 1][1] = t4[3];
            }
#pragma unroll
            for (int mt = 0; mt < 4; mt++)
#pragma unroll
                for (int nt = 0; nt < 4; nt++)
                    mma_f16(acc[mt][nt], af[mt], bf[nt]);
        }
    }

#pragma unroll
    for (int nt = 0; nt < 4; nt++) {
        int col = n0 + warp_n * 32 + nt * 8 + c * 2;
        float bx = __ldg(&bias[col]);
        float by = __ldg(&bias[col + 1]);
#pragma unroll
        for (int mt = 0; mt < 4; mt++) {
            int row0 = m0 + warp_m * 64 + mt * 16 + r;
            if (MODE == 0) {
                __half2 h0 = __floats2half2_rn(acc[mt][nt][0] + bx,
                                               acc[mt][nt][1] + by);
                __half2 h1 = __floats2half2_rn(acc[mt][nt][2] + bx,
                                               acc[mt][nt][3] + by);
                int head = col >> 6;
                int d = col & 63;
                int b = row0 >> 11;
                int t = row0 & 2047;
                if (zsel == 2) {
                    __half* vt = g_vth + (((size_t)b * HH + head) * HD) * TT;
                    vt[(size_t)d * TT + t]           = __low2half(h0);
                    vt[(size_t)(d + 1) * TT + t]     = __high2half(h0);
                    vt[(size_t)d * TT + t + 8]       = __low2half(h1);
                    vt[(size_t)(d + 1) * TT + t + 8] = __high2half(h1);
                } else {
                    __half* out = (zsel == 0) ? g_qh : g_kh;
                    size_t base = (((size_t)b * HH + head) * TT + t) * HD + d;
                    *(__half2*)&out[base] = h0;
                    *(__half2*)&out[base + 8 * HD] = h1;
                }
            } else {
                float2 v0, v1;
                v0.x = acc[mt][nt][0] + bx;
                v0.y = acc[mt][nt][1] + by;
                v1.x = acc[mt][nt][2] + bx;
                v1.y = acc[mt][nt][3] + by;
                *(float2*)&OutDirect[(size_t)row0 * DD + col] = v0;
                *(float2*)&OutDirect[(size_t)(row0 + 8) * DD + col] = v1;
            }
        }
    }
}

// ---------------------------------------------------------------------------
// fp16 flash attention with ldmatrix fragment loads.
// 256 threads / 8 warps, Q-tile 128, one 16-row m-frag per warp.
// P stays in registers (C-frag -> A-frag half2 pack).
// K/V 64-key tiles double-buffered via cp.async.
// Smem 55296B: sQ 128x72h | sK[2] 64x72h | sV[2] 64x72h.
// ---------------------------------------------------------------------------
__global__ __launch_bounds__(256, 2) void attn_fa()
{
    extern __shared__ __half sa[];

    int bh = blockIdx.y;
    int m0 = blockIdx.x * 128;
    int tid = threadIdx.x;
    int wid = tid >> 5;
    int lane = tid & 31;
    int r = lane >> 2;
    int c = lane & 3;
    int sub = lane >> 3;
    int rin = lane & 7;

    uint32_t sbase = (uint32_t)__cvta_generic_to_shared(sa);

    const __half* Qb  = g_qh + (size_t)bh * TT * HD;
    const __half* Kb  = g_kh + (size_t)bh * TT * HD;
    const __half* Vtb = g_vth + (size_t)bh * HD * TT;  // [d][T]
    __half* Ob        = g_oh + (size_t)bh * TT * HD;

    const int NT = blockIdx.x * 2 + 2;

    // K/V tile 0
#pragma unroll
    for (int i = 0; i < 2; i++) {
        int idx = tid + i * 256;
        int row = idx >> 3;
        int ch = idx & 7;
        cpasync16(&sa[9216 + row * HSTR + ch * 8],
                  Kb + (size_t)row * HD + ch * 8);
        cpasync16(&sa[18432 + row * HSTR + ch * 8],
                  Vtb + (size_t)row * TT + ch * 8);
    }
    CP_COMMIT();

    // Q tile -> smem
#pragma unroll
    for (int i = 0; i < 4; i++) {
        int idx = tid + i * 256;
        int row = idx >> 3;
        int ch = idx & 7;
        *(uint4*)&sa[row * HSTR + ch * 8] =
            *(const uint4*)&Qb[(size_t)(m0 + row) * HD + ch * 8];
    }
    __syncthreads();

    int lr = wid * 16 + r;
    // ldmatrix offsets (halves)
    int q_off = (wid * 16 + (sub & 1) * 8 + rin) * HSTR + (sub >> 1) * 8;
    int kv_off[4];
#pragma unroll
    for (int j = 0; j < 4; j++)
        kv_off[j] = ((2 * j + (sub >> 1)) * 8 + rin) * HSTR + (sub & 1) * 8;

    uint32_t qf[4][4];
#pragma unroll
    for (int kc = 0; kc < 4; kc++)
        ldsm_x4(qf[kc], sbase + (q_off + kc * 16) * 2);

    float o[8][4];
#pragma unroll
    for (int nt = 0; nt < 8; nt++)
#pragma unroll
        for (int i = 0; i < 4; i++) o[nt][i] = 0.f;

    float mr0 = -INFINITY, mr1 = -INFINITY;
    float l0 = 0.f, l1 = 0.f;
    int rg0 = m0 + lr;
    int rg1 = rg0 + 8;

    for (int s = 0; s < NT; s++) {
        int kt = s * 64;
        CP_WAIT0();
        __syncthreads();

        if (s + 1 < NT) {
            int kt2 = (s + 1) * 64;
            int st2 = (s + 1) & 1;
#pragma unroll
            for (int i = 0; i < 2; i++) {
                int idx = tid + i * 256;
                int row = idx >> 3;
                int ch = idx & 7;
                cpasync16(&sa[9216 + st2 * 4608 + row * HSTR + ch * 8],
                          Kb + (size_t)(kt2 + row) * HD + ch * 8);
                cpasync16(&sa[18432 + st2 * 4608 + row * HSTR + ch * 8],
                          Vtb + (size_t)row * TT + kt2 + ch * 8);
            }
            CP_COMMIT();
        }

        uint32_t kB = sbase + (9216 + (s & 1) * 4608) * 2;
        uint32_t vB = sbase + (18432 + (s & 1) * 4608) * 2;

        // ---- S = Q K^T ----
        float sc[8][4];
#pragma unroll
        for (int nt = 0; nt < 8; nt++)
#pragma unroll
            for (int i = 0; i < 4; i++) sc[nt][i] = 0.f;
#pragma unroll
        for (int kc = 0; kc < 4; kc++) {
#pragma unroll
            for (int j = 0; j < 4; j++) {
                uint32_t t4[4];
                ldsm_x4(t4, kB + (kv_off[j] + kc * 16) * 2);
                mma_f16(sc[2 * j],     qf[kc], t4);
                mma_f16(sc[2 * j + 1], qf[kc], t4 + 2);
            }
        }

        // ---- scale, mask, online softmax; P packed to half2 in regs ----
        bool need_mask = (kt + 63 > m0);
        float mx0 = mr0, mx1 = mr1;
#pragma unroll
        for (int nt = 0; nt < 8; nt++) {
            float* sv = sc[nt];
            sv[0] *= SCALE_F; sv[1] *= SCALE_F;
            sv[2] *= SCALE_F; sv[3] *= SCALE_F;
            if (need_mask) {
                int col0 = kt + nt * 8 + 2 * c;
                if (col0     > rg0) sv[0] = -INFINITY;
                if (col0 + 1 > rg0) sv[1] = -INFINITY;
                if (col0     > rg1) sv[2] = -INFINITY;
                if (col0 + 1 > rg1) sv[3] = -INFINITY;
            }
            mx0 = fmaxf(mx0, fmaxf(sv[0], sv[1]));
            mx1 = fmaxf(mx1, fmaxf(sv[2], sv[3]));
        }
        mx0 = fmaxf(mx0, __shfl_xor_sync(0xffffffffu, mx0, 1));
        mx0 = fmaxf(mx0, __shfl_xor_sync(0xffffffffu, mx0, 2));
        mx1 = fmaxf(mx1, __shfl_xor_sync(0xffffffffu, mx1, 1));
        mx1 = fmaxf(mx1, __shfl_xor_sync(0xffffffffu, mx1, 2));

        float a0 = __expf(mr0 - mx0);
        float a1 = __expf(mr1 - mx1);
        float sum0 = 0.f, sum1 = 0.f;
        uint32_t pk[8][2];
#pragma unroll
        for (int nt = 0; nt < 8; nt++) {
            __half2 h01 = __floats2half2_rn(__expf(sc[nt][0] - mx0),
                                            __expf(sc[nt][1] - mx0));
            __half2 h23 = __floats2half2_rn(__expf(sc[nt][2] - mx1),
                                            __expf(sc[nt][3] - mx1));
            pk[nt][0] = *(uint32_t*)&h01;
            pk[nt][1] = *(uint32_t*)&h23;
            float2 f01 = __half22float2(h01);
            float2 f23 = __half22float2(h23);
            sum0 += f01.x + f01.y;
            sum1 += f23.x + f23.y;
        }
        sum0 += __shfl_xor_sync(0xffffffffu, sum0, 1);
        sum0 += __shfl_xor_sync(0xffffffffu, sum0, 2);
        sum1 += __shfl_xor_sync(0xffffffffu, sum1, 1);
        sum1 += __shfl_xor_sync(0xffffffffu, sum1, 2);
        l0 = l0 * a0 + sum0;
        l1 = l1 * a1 + sum1;
#pragma unroll
        for (int nt = 0; nt < 8; nt++) {
            o[nt][0] *= a0; o[nt][1] *= a0;
            o[nt][2] *= a1; o[nt][3] *= a1;
        }
        mr0 = mx0; mr1 = mx1;

        // ---- O += P V ----
#pragma unroll
        for (int kc = 0; kc < 4; kc++) {
            uint32_t af[4];
            af[0] = pk[2 * kc][0];
            af[1] = pk[2 * kc][1];
            af[2] = pk[2 * kc + 1][0];
            af[3] = pk[2 * kc + 1][1];
#pragma unroll
            for (int j = 0; j < 4; j++) {
                uint32_t t4[4];
                ldsm_x4(t4, vB + (kv_off[j] + kc * 16) * 2);
                mma_f16(o[2 * j],     af, t4);
                mma_f16(o[2 * j + 1], af, t4 + 2);
            }
        }
    }

    // ---- output as fp16 (feeds MODE 1 GEMM) ----
    float i0 = 1.f / l0, i1 = 1.f / l1;
#pragma unroll
    for (int nt = 0; nt < 8; nt++) {
        *(__half2*)&Ob[(size_t)rg0 * HD + nt * 8 + 2 * c] =
            __floats2half2_rn(o[nt][0] * i0, o[nt][1] * i0);
        *(__half2*)&Ob[(size_t)rg1 * HD + nt * 8 + 2 * c] =
            __floats2half2_rn(o[nt][2] * i1, o[nt][3] * i1);
    }
}

extern "C" void kernel_launch(void* const* d_in, const int* in_sizes, int n_in,
                              void* d_out, int out_size)
{
    const float* x  = (const float*)d_in[0];
    const float* Wq = (const float*)d_in[1];
    const float* bq = (const float*)d_in[2];
    const float* Wk = (const float*)d_in[3];
    const float* bk = (const float*)d_in[4];
    const float* Wv = (const float*)d_in[5];
    const float* bv = (const float*)d_in[6];
    const float* Wo = (const float*)d_in[7];
    const float* bo = (const float*)d_in[8];
    float* out = (float*)d_out;

    const int GEMM_SMEM = 4 * TILE_H * 2;   // 73728 B
    const int ATTN_SMEM = 27648 * 2;        // 55296 B
    cudaFuncSetAttribute(gemm_tc<0>, cudaFuncAttributeMaxDynamicSharedMemorySize,
                         GEMM_SMEM);
    cudaFuncSetAttribute(gemm_tc<1>, cudaFuncAttributeMaxDynamicSharedMemorySize,
                         GEMM_SMEM);
    cudaFuncSetAttribute(attn_fa, cudaFuncAttributeMaxDynamicSharedMemorySize,
                         ATTN_SMEM);

    round_x<<<(BB * TT * DD) / (256 * 4), 256>>>(x);

    dim3 gt(32, 32, 4);
    transpose_w<<<gt, dim3(32, 8)>>>(Wq, Wk, Wv, Wo);

    dim3 g1(DD / 128, (BB * TT) / 128, 3);
    gemm_tc<0><<<g1, 256, GEMM_SMEM>>>(bq, bk, bv, nullptr);

    dim3 g2(TT / 128, BB * HH);
    attn_fa<<<g2, 256, ATTN_SMEM>>>();

    dim3 g3(DD / 128, (BB * TT) / 128);
    gemm_tc<1><<<g3, 256, GEMM_SMEM>>>(bo, nullptr, nullptr, out);
}

// round 13
// speedup vs baseline: 2.1903x; 1.0242x over previous
#include <cuda_runtime.h>
#include <cuda_fp16.h>
#include <math.h>
#include <stdint.h>

#define BB 4
#define TT 2048
#define DD 1024
#define HH 16
#define HD 64
#define SCALE_F 0.125f   // 1/sqrt(64)
#define QSCALE (SCALE_F * 1.44269504088896f)   // fold log2(e): exp2-domain scores

// fp16 scratch. g_qh (PRE-SCALED by QSCALE), g_kh, g_oh: [B, H, T, hd].
// g_vth: [B, H, hd, T].
__device__ __half g_qh[(size_t)BB * HH * TT * HD];
__device__ __half g_kh[(size_t)BB * HH * TT * HD];
__device__ __half g_vth[(size_t)BB * HH * TT * HD];
__device__ __half g_oh[(size_t)BB * HH * TT * HD];
__device__ __half g_xh[(size_t)BB * TT * DD];          // fp16 X
__device__ __half g_wth[(size_t)4 * DD * DD];          // W^T [N][K] fp16

__device__ __forceinline__ void mma_f16(float* d, const uint32_t* a,
                                        const uint32_t* b) {
    asm volatile(
        "mma.sync.aligned.m16n8k16.row.col.f32.f16.f16.f32 "
        "{%0,%1,%2,%3}, {%4,%5,%6,%7}, {%8,%9}, {%0,%1,%2,%3};"
        : "+f"(d[0]), "+f"(d[1]), "+f"(d[2]), "+f"(d[3])
        : "r"(a[0]), "r"(a[1]), "r"(a[2]), "r"(a[3]),
          "r"(b[0]), "r"(b[1]));
}

__device__ __forceinline__ void ldsm_x4(uint32_t* d, uint32_t saddr) {
    asm volatile(
        "ldmatrix.sync.aligned.m8n8.x4.shared.b16 {%0,%1,%2,%3}, [%4];"
        : "=r"(d[0]), "=r"(d[1]), "=r"(d[2]), "=r"(d[3]) : "r"(saddr));
}

__device__ __forceinline__ float ex2(float x) {
    float y;
    asm("ex2.approx.f32 %0, %1;" : "=f"(y) : "f"(x));
    return y;
}

__device__ __forceinline__ void cpasync16(void* sptr, const void* gptr) {
    uint32_t sa = (uint32_t)__cvta_generic_to_shared(sptr);
    asm volatile("cp.async.ca.shared.global [%0], [%1], 16;"
                 :: "r"(sa), "l"(gptr));
}
#define CP_COMMIT() asm volatile("cp.async.commit_group;" ::: "memory")
#define CP_WAIT0()  asm volatile("cp.async.wait_group 0;" ::: "memory")

// ---------------------------------------------------------------------------
// X -> fp16
// ---------------------------------------------------------------------------
__global__ __launch_bounds__(256) void round_x(const float* __restrict__ x)
{
    size_t i = ((size_t)blockIdx.x * 256 + threadIdx.x) * 4;
    float4 v = *(const float4*)&x[i];
    __half2 h0 = __floats2half2_rn(v.x, v.y);
    __half2 h1 = __floats2half2_rn(v.z, v.w);
    *(uint2*)&g_xh[i] = make_uint2(*(uint32_t*)&h0, *(uint32_t*)&h1);
}

// ---------------------------------------------------------------------------
// Weight transpose: W [K,N] f32 -> g_wth slice [N,K] fp16
// ---------------------------------------------------------------------------
__global__ __launch_bounds__(256) void transpose_w(
    const float* __restrict__ Wq, const float* __restrict__ Wk,
    const float* __restrict__ Wv, const float* __restrict__ Wo)
{
    const float* src = (blockIdx.z == 0) ? Wq : (blockIdx.z == 1) ? Wk
                     : (blockIdx.z == 2) ? Wv : Wo;
    __half* dst = g_wth + (size_t)blockIdx.z * DD * DD;

    __shared__ float tile[32][33];
    int x = blockIdx.x * 32 + threadIdx.x;
    int y0 = blockIdx.y * 32;
#pragma unroll
    for (int j = threadIdx.y; j < 32; j += 8)
        tile[j][threadIdx.x] = src[(size_t)(y0 + j) * DD + x];
    __syncthreads();
    int x2 = y0 + threadIdx.x;
    int y2 = blockIdx.x * 32;
#pragma unroll
    for (int j = threadIdx.y; j < 32; j += 8)
        dst[(size_t)(y2 + j) * DD + x2] = __float2half_rn(tile[threadIdx.x][j]);
}

// ---------------------------------------------------------------------------
// fp16 cp.async 2-stage GEMM, BK=64, ldmatrix fragment loads.
// MODE 0: A = g_xh; z=0 -> g_qh (scaled by QSCALE), z=1 -> g_kh,
//         z=2 -> g_vth (transposed).
// MODE 1: A = g_oh (gathered), out = d_out f32 [B*T, D].
// ---------------------------------------------------------------------------
#define BKH 64
#define HSTR 72
#define TILE_H (128 * HSTR)     // 9216 halves

template <int MODE>
__global__ __launch_bounds__(256) void gemm_tc(
    const float* __restrict__ b0, const float* __restrict__ b1,
    const float* __restrict__ b2, float* __restrict__ OutDirect)
{
    extern __shared__ __half smh[];

    int tid = threadIdx.x;
    int wid = tid >> 5;
    int lane = tid & 31;
    int warp_m = wid & 1;
    int warp_n = wid >> 1;
    int r = lane >> 2;
    int c = lane & 3;
    int sub = lane >> 3;
    int rin = lane & 7;
    int n0 = blockIdx.x * 128;
    int m0 = blockIdx.y * 128;

    uint32_t sbase = (uint32_t)__cvta_generic_to_shared(smh);

    const __half* Wt;
    const float* bias;
    const __half* Ain;
    int zsel = 0;
    if (MODE == 0) {
        zsel = blockIdx.z;
        Wt = g_wth + (size_t)zsel * DD * DD;
        bias = (zsel == 0) ? b0 : (zsel == 1) ? b1 : b2;
        Ain = g_xh;
    } else {
        Wt = g_wth + (size_t)3 * DD * DD;
        bias = b0;
        Ain = g_oh;
    }

    auto load_stage = [&](int st, int kt) {
#pragma unroll
        for (int i = 0; i < 4; i++) {
            int idx = tid + i * 256;
            int row = idx >> 3;
            int ch = idx & 7;
            const __half* srcA;
            if (MODE == 0) {
                srcA = Ain + (size_t)(m0 + row) * DD + kt + ch * 8;
            } else {
                int m = m0 + row;
                int b = m >> 11;
                int t = m & 2047;
                int h = kt >> 6;
                srcA = Ain + (((size_t)b * HH + h) * TT + t) * HD + ch * 8;
            }
            cpasync16(&smh[st * TILE_H + row * HSTR + ch * 8], srcA);
            cpasync16(&smh[2 * TILE_H + st * TILE_H + row * HSTR + ch * 8],
                      Wt + (size_t)(n0 + row) * DD + kt + ch * 8);
        }
        CP_COMMIT();
    };

    int a_off = (warp_m * 64 + (sub & 1) * 8 + rin) * HSTR + (sub >> 1) * 8;
    int b_off[2];
#pragma unroll
    for (int j = 0; j < 2; j++)
        b_off[j] = (warp_n * 32 + (2 * j + (sub >> 1)) * 8 + rin) * HSTR
                 + (sub & 1) * 8;

    float acc[4][4][4];
#pragma unroll
    for (int mt = 0; mt < 4; mt++)
#pragma unroll
        for (int nt = 0; nt < 4; nt++)
#pragma unroll
            for (int i = 0; i < 4; i++) acc[mt][nt][i] = 0.f;

    const int NIT = DD / BKH;
    load_stage(0, 0);

    for (int it = 0; it < NIT; it++) {
        CP_WAIT0();
        __syncthreads();

        if (it + 1 < NIT)
            load_stage((it + 1) & 1, (it + 1) * BKH);

        uint32_t aB = sbase + ((it & 1) * TILE_H) * 2;
        uint32_t bB = sbase + (2 * TILE_H + (it & 1) * TILE_H) * 2;
#pragma unroll
        for (int ks = 0; ks < 4; ks++) {
            int k0 = ks * 16;
            uint32_t af[4][4], bf[4][2];
#pragma unroll
            for (int mt = 0; mt < 4; mt++)
                ldsm_x4(af[mt], aB + (a_off + mt * 16 * HSTR + k0) * 2);
#pragma unroll
            for (int j = 0; j < 2; j++) {
                uint32_t t4[4];
                ldsm_x4(t4, bB + (b_off[j] + k0) * 2);
                bf[2 * j][0] = t4[0]; bf[2 * j][1] = t4[1];
                bf[2 * j + 1][0] = t4[2]; bf[2 * j + 1][1] = t4[3];
            }
#pragma unroll
            for (int mt = 0; mt < 4; mt++)
#pragma unroll
                for (int nt = 0; nt < 4; nt++)
                    mma_f16(acc[mt][nt], af[mt], bf[nt]);
        }
    }

#pragma unroll
    for (int nt = 0; nt < 4; nt++) {
        int col = n0 + warp_n * 32 + nt * 8 + c * 2;
        float bx = __ldg(&bias[col]);
        float by = __ldg(&bias[col + 1]);
#pragma unroll
        for (int mt = 0; mt < 4; mt++) {
            int row0 = m0 + warp_m * 64 + mt * 16 + r;
            if (MODE == 0) {
                float e0 = acc[mt][nt][0] + bx;
                float e1 = acc[mt][nt][1] + by;
                float e2 = acc[mt][nt][2] + bx;
                float e3 = acc[mt][nt][3] + by;
                if (zsel == 0) {        // pre-scale Q into exp2 domain
                    e0 *= QSCALE; e1 *= QSCALE; e2 *= QSCALE; e3 *= QSCALE;
                }
                __half2 h0 = __floats2half2_rn(e0, e1);
                __half2 h1 = __floats2half2_rn(e2, e3);
                int head = col >> 6;
                int d = col & 63;
                int b = row0 >> 11;
                int t = row0 & 2047;
                if (zsel == 2) {
                    __half* vt = g_vth + (((size_t)b * HH + head) * HD) * TT;
                    vt[(size_t)d * TT + t]           = __low2half(h0);
                    vt[(size_t)(d + 1) * TT + t]     = __high2half(h0);
                    vt[(size_t)d * TT + t + 8]       = __low2half(h1);
                    vt[(size_t)(d + 1) * TT + t + 8] = __high2half(h1);
                } else {
                    __half* out = (zsel == 0) ? g_qh : g_kh;
                    size_t base = (((size_t)b * HH + head) * TT + t) * HD + d;
                    *(__half2*)&out[base] = h0;
                    *(__half2*)&out[base + 8 * HD] = h1;
                }
            } else {
                float2 v0, v1;
                v0.x = acc[mt][nt][0] + bx;
                v0.y = acc[mt][nt][1] + by;
                v1.x = acc[mt][nt][2] + bx;
                v1.y = acc[mt][nt][3] + by;
                *(float2*)&OutDirect[(size_t)row0 * DD + col] = v0;
                *(float2*)&OutDirect[(size_t)(row0 + 8) * DD + col] = v1;
            }
        }
    }
}

// ---------------------------------------------------------------------------
// fp16 flash attention; scores arrive in exp2-domain (Q pre-scaled).
// 256 threads / 8 warps, Q-tile 128, heaviest blocks scheduled first.
// ---------------------------------------------------------------------------
__global__ __launch_bounds__(256, 2) void attn_fa()
{
    extern __shared__ __half sa[];

    int bh = blockIdx.y;
    int qt = gridDim.x - 1 - blockIdx.x;   // LPT: heavy (large-NT) blocks first
    int m0 = qt * 128;
    int tid = threadIdx.x;
    int wid = tid >> 5;
    int lane = tid & 31;
    int r = lane >> 2;
    int c = lane & 3;
    int sub = lane >> 3;
    int rin = lane & 7;

    uint32_t sbase = (uint32_t)__cvta_generic_to_shared(sa);

    const __half* Qb  = g_qh + (size_t)bh * TT * HD;
    const __half* Kb  = g_kh + (size_t)bh * TT * HD;
    const __half* Vtb = g_vth + (size_t)bh * HD * TT;
    __half* Ob        = g_oh + (size_t)bh * TT * HD;

    const int NT = qt * 2 + 2;

#pragma unroll
    for (int i = 0; i < 2; i++) {
        int idx = tid + i * 256;
        int row = idx >> 3;
        int ch = idx & 7;
        cpasync16(&sa[9216 + row * HSTR + ch * 8],
                  Kb + (size_t)row * HD + ch * 8);
        cpasync16(&sa[18432 + row * HSTR + ch * 8],
                  Vtb + (size_t)row * TT + ch * 8);
    }
    CP_COMMIT();

#pragma unroll
    for (int i = 0; i < 4; i++) {
        int idx = tid + i * 256;
        int row = idx >> 3;
        int ch = idx & 7;
        *(uint4*)&sa[row * HSTR + ch * 8] =
            *(const uint4*)&Qb[(size_t)(m0 + row) * HD + ch * 8];
    }
    __syncthreads();

    int lr = wid * 16 + r;
    int q_off = (wid * 16 + (sub & 1) * 8 + rin) * HSTR + (sub >> 1) * 8;
    int kv_off[4];
#pragma unroll
    for (int j = 0; j < 4; j++)
        kv_off[j] = ((2 * j + (sub >> 1)) * 8 + rin) * HSTR + (sub & 1) * 8;

    uint32_t qf[4][4];
#pragma unroll
    for (int kc = 0; kc < 4; kc++)
        ldsm_x4(qf[kc], sbase + (q_off + kc * 16) * 2);

    float o[8][4];
#pragma unroll
    for (int nt = 0; nt < 8; nt++)
#pragma unroll
        for (int i = 0; i < 4; i++) o[nt][i] = 0.f;

    float mr0 = -INFINITY, mr1 = -INFINITY;
    float l0 = 0.f, l1 = 0.f;
    int rg0 = m0 + lr;
    int rg1 = rg0 + 8;

    for (int s = 0; s < NT; s++) {
        int kt = s * 64;
        CP_WAIT0();
        __syncthreads();

        if (s + 1 < NT) {
            int kt2 = (s + 1) * 64;
            int st2 = (s + 1) & 1;
#pragma unroll
            for (int i = 0; i < 2; i++) {
                int idx = tid + i * 256;
                int row = idx >> 3;
                int ch = idx & 7;
                cpasync16(&sa[9216 + st2 * 4608 + row * HSTR + ch * 8],
                          Kb + (size_t)(kt2 + row) * HD + ch * 8);
                cpasync16(&sa[18432 + st2 * 4608 + row * HSTR + ch * 8],
                          Vtb + (size_t)row * TT + kt2 + ch * 8);
            }
            CP_COMMIT();
        }

        uint32_t kB = sbase + (9216 + (s & 1) * 4608) * 2;
        uint32_t vB = sbase + (18432 + (s & 1) * 4608) * 2;

        // ---- S = Q K^T (already exp2-domain) ----
        float sc[8][4];
#pragma unroll
        for (int nt = 0; nt < 8; nt++)
#pragma unroll
            for (int i = 0; i < 4; i++) sc[nt][i] = 0.f;
#pragma unroll
        for (int kc = 0; kc < 4; kc++) {
#pragma unroll
            for (int j = 0; j < 4; j++) {
                uint32_t t4[4];
                ldsm_x4(t4, kB + (kv_off[j] + kc * 16) * 2);
                mma_f16(sc[2 * j],     qf[kc], t4);
                mma_f16(sc[2 * j + 1], qf[kc], t4 + 2);
            }
        }

        // ---- mask + online softmax (exp2) ----
        bool need_mask = (kt + 63 > m0);
        float mx0 = mr0, mx1 = mr1;
#pragma unroll
        for (int nt = 0; nt < 8; nt++) {
            float* sv = sc[nt];
            if (need_mask) {
                int col0 = kt + nt * 8 + 2 * c;
                if (col0     > rg0) sv[0] = -INFINITY;
                if (col0 + 1 > rg0) sv[1] = -INFINITY;
                if (col0     > rg1) sv[2] = -INFINITY;
                if (col0 + 1 > rg1) sv[3] = -INFINITY;
            }
            mx0 = fmaxf(mx0, fmaxf(sv[0], sv[1]));
            mx1 = fmaxf(mx1, fmaxf(sv[2], sv[3]));
        }
        mx0 = fmaxf(mx0, __shfl_xor_sync(0xffffffffu, mx0, 1));
        mx0 = fmaxf(mx0, __shfl_xor_sync(0xffffffffu, mx0, 2));
        mx1 = fmaxf(mx1, __shfl_xor_sync(0xffffffffu, mx1, 1));
        mx1 = fmaxf(mx1, __shfl_xor_sync(0xffffffffu, mx1, 2));

        float a0 = ex2(mr0 - mx0);
        float a1 = ex2(mr1 - mx1);
        float sum0 = 0.f, sum1 = 0.f;
        uint32_t pk[8][2];
#pragma unroll
        for (int nt = 0; nt < 8; nt++) {
            __half2 h01 = __floats2half2_rn(ex2(sc[nt][0] - mx0),
                                            ex2(sc[nt][1] - mx0));
            __half2 h23 = __floats2half2_rn(ex2(sc[nt][2] - mx1),
                                            ex2(sc[nt][3] - mx1));
            pk[nt][0] = *(uint32_t*)&h01;
            pk[nt][1] = *(uint32_t*)&h23;
            float2 f01 = __half22float2(h01);
            float2 f23 = __half22float2(h23);
            sum0 += f01.x + f01.y;
            sum1 += f23.x + f23.y;
        }
        sum0 += __shfl_xor_sync(0xffffffffu, sum0, 1);
        sum0 += __shfl_xor_sync(0xffffffffu, sum0, 2);
        sum1 += __shfl_xor_sync(0xffffffffu, sum1, 1);
        sum1 += __shfl_xor_sync(0xffffffffu, sum1, 2);
        l0 = l0 * a0 + sum0;
        l1 = l1 * a1 + sum1;
#pragma unroll
        for (int nt = 0; nt < 8; nt++) {
            o[nt][0] *= a0; o[nt][1] *= a0;
            o[nt][2] *= a1; o[nt][3] *= a1;
        }
        mr0 = mx0; mr1 = mx1;

        // ---- O += P V ----
#pragma unroll
        for (int kc = 0; kc < 4; kc++) {
            uint32_t af[4];
            af[0] = pk[2 * kc][0];
            af[1] = pk[2 * kc][1];
            af[2] = pk[2 * kc + 1][0];
            af[3] = pk[2 * kc + 1][1];
#pragma unroll
            for (int j = 0; j < 4; j++) {
                uint32_t t4[4];
                ldsm_x4(t4, vB + (kv_off[j] + kc * 16) * 2);
                mma_f16(o[2 * j],     af, t4);
                mma_f16(o[2 * j + 1], af, t4 + 2);
            }
        }
    }

    float i0 = 1.f / l0, i1 = 1.f / l1;
#pragma unroll
    for (int nt = 0; nt < 8; nt++) {
        *(__half2*)&Ob[(size_t)rg0 * HD + nt * 8 + 2 * c] =
            __floats2half2_rn(o[nt][0] * i0, o[nt][1] * i0);
        *(__half2*)&Ob[(size_t)rg1 * HD + nt * 8 + 2 * c] =
            __floats2half2_rn(o[nt][2] * i1, o[nt][3] * i1);
    }
}

extern "C" void kernel_launch(void* const* d_in, const int* in_sizes, int n_in,
                              void* d_out, int out_size)
{
    const float* x  = (const float*)d_in[0];
    const float* Wq = (const float*)d_in[1];
    const float* bq = (const float*)d_in[2];
    const float* Wk = (const float*)d_in[3];
    const float* bk = (const float*)d_in[4];
    const float* Wv = (const float*)d_in[5];
    const float* bv = (const float*)d_in[6];
    const float* Wo = (const float*)d_in[7];
    const float* bo = (const float*)d_in[8];
    float* out = (float*)d_out;

    const int GEMM_SMEM = 4 * TILE_H * 2;   // 73728 B
    const int ATTN_SMEM = 27648 * 2;        // 55296 B
    cudaFuncSetAttribute(gemm_tc<0>, cudaFuncAttributeMaxDynamicSharedMemorySize,
                         GEMM_SMEM);
    cudaFuncSetAttribute(gemm_tc<1>, cudaFuncAttributeMaxDynamicSharedMemorySize,
                         GEMM_SMEM);
    cudaFuncSetAttribute(attn_fa, cudaFuncAttributeMaxDynamicSharedMemorySize,
                         ATTN_SMEM);

    round_x<<<(BB * TT * DD) / (256 * 4), 256>>>(x);

    dim3 gt(32, 32, 4);
    transpose_w<<<gt, dim3(32, 8)>>>(Wq, Wk, Wv, Wo);

    dim3 g1(DD / 128, (BB * TT) / 128, 3);
    gemm_tc<0><<<g1, 256, GEMM_SMEM>>>(bq, bk, bv, nullptr);

    dim3 g2(TT / 128, BB * HH);
    attn_fa<<<g2, 256, ATTN_SMEM>>>();

    dim3 g3(DD / 128, (BB * TT) / 128);
    gemm_tc<1><<<g3, 256, GEMM_SMEM>>>(bo, nullptr, nullptr, out);
}

// round 14
// speedup vs baseline: 2.2421x; 1.0236x over previous
#include <cuda_runtime.h>
#include <cuda_fp16.h>
#include <math.h>
#include <stdint.h>

#define BB 4
#define TT 2048
#define DD 1024
#define HH 16
#define HD 64
#define SCALE_F 0.125f   // 1/sqrt(64)
#define QSCALE (SCALE_F * 1.44269504088896f)   // fold log2(e): exp2-domain scores

// fp16 scratch. g_qh (PRE-SCALED by QSCALE), g_kh, g_oh: [B, H, T, hd].
// g_vth: [B, H, hd, T].
__device__ __half g_qh[(size_t)BB * HH * TT * HD];
__device__ __half g_kh[(size_t)BB * HH * TT * HD];
__device__ __half g_vth[(size_t)BB * HH * TT * HD];
__device__ __half g_oh[(size_t)BB * HH * TT * HD];
__device__ __half g_xh[(size_t)BB * TT * DD];          // fp16 X
__device__ __half g_wth[(size_t)4 * DD * DD];          // W^T [N][K] fp16

__device__ __forceinline__ void mma_f16(float* d, const uint32_t* a,
                                        const uint32_t* b) {
    asm volatile(
        "mma.sync.aligned.m16n8k16.row.col.f32.f16.f16.f32 "
        "{%0,%1,%2,%3}, {%4,%5,%6,%7}, {%8,%9}, {%0,%1,%2,%3};"
        : "+f"(d[0]), "+f"(d[1]), "+f"(d[2]), "+f"(d[3])
        : "r"(a[0]), "r"(a[1]), "r"(a[2]), "r"(a[3]),
          "r"(b[0]), "r"(b[1]));
}

__device__ __forceinline__ void ldsm_x4(uint32_t* d, uint32_t saddr) {
    asm volatile(
        "ldmatrix.sync.aligned.m8n8.x4.shared.b16 {%0,%1,%2,%3}, [%4];"
        : "=r"(d[0]), "=r"(d[1]), "=r"(d[2]), "=r"(d[3]) : "r"(saddr));
}

__device__ __forceinline__ float ex2(float x) {
    float y;
    asm("ex2.approx.f32 %0, %1;" : "=f"(y) : "f"(x));
    return y;
}
// two-wide fp16 exp2: input packed half2, output packed half2
__device__ __forceinline__ uint32_t ex2_h2(uint32_t x) {
    uint32_t y;
    asm("ex2.approx.f16x2 %0, %1;" : "=r"(y) : "r"(x));
    return y;
}

__device__ __forceinline__ void cpasync16(void* sptr, const void* gptr) {
    uint32_t sa = (uint32_t)__cvta_generic_to_shared(sptr);
    asm volatile("cp.async.ca.shared.global [%0], [%1], 16;"
                 :: "r"(sa), "l"(gptr));
}
#define CP_COMMIT() asm volatile("cp.async.commit_group;" ::: "memory")
#define CP_WAIT0()  asm volatile("cp.async.wait_group 0;" ::: "memory")

// ---------------------------------------------------------------------------
// X -> fp16
// ---------------------------------------------------------------------------
__global__ __launch_bounds__(256) void round_x(const float* __restrict__ x)
{
    size_t i = ((size_t)blockIdx.x * 256 + threadIdx.x) * 4;
    float4 v = *(const float4*)&x[i];
    __half2 h0 = __floats2half2_rn(v.x, v.y);
    __half2 h1 = __floats2half2_rn(v.z, v.w);
    *(uint2*)&g_xh[i] = make_uint2(*(uint32_t*)&h0, *(uint32_t*)&h1);
}

// ---------------------------------------------------------------------------
// Weight transpose: W [K,N] f32 -> g_wth slice [N,K] fp16
// ---------------------------------------------------------------------------
__global__ __launch_bounds__(256) void transpose_w(
    const float* __restrict__ Wq, const float* __restrict__ Wk,
    const float* __restrict__ Wv, const float* __restrict__ Wo)
{
    const float* src = (blockIdx.z == 0) ? Wq : (blockIdx.z == 1) ? Wk
                     : (blockIdx.z == 2) ? Wv : Wo;
    __half* dst = g_wth + (size_t)blockIdx.z * DD * DD;

    __shared__ float tile[32][33];
    int x = blockIdx.x * 32 + threadIdx.x;
    int y0 = blockIdx.y * 32;
#pragma unroll
    for (int j = threadIdx.y; j < 32; j += 8)
        tile[j][threadIdx.x] = src[(size_t)(y0 + j) * DD + x];
    __syncthreads();
    int x2 = y0 + threadIdx.x;
    int y2 = blockIdx.x * 32;
#pragma unroll
    for (int j = threadIdx.y; j < 32; j += 8)
        dst[(size_t)(y2 + j) * DD + x2] = __float2half_rn(tile[threadIdx.x][j]);
}

// ---------------------------------------------------------------------------
// fp16 cp.async 2-stage GEMM, BK=64, ldmatrix fragment loads. (unchanged)
// MODE 0: A = g_xh; z=0 -> g_qh (scaled by QSCALE), z=1 -> g_kh,
//         z=2 -> g_vth (transposed).
// MODE 1: A = g_oh (gathered), out = d_out f32 [B*T, D].
// ---------------------------------------------------------------------------
#define BKH 64
#define HSTR 72
#define TILE_H (128 * HSTR)     // 9216 halves

template <int MODE>
__global__ __launch_bounds__(256) void gemm_tc(
    const float* __restrict__ b0, const float* __restrict__ b1,
    const float* __restrict__ b2, float* __restrict__ OutDirect)
{
    extern __shared__ __half smh[];

    int tid = threadIdx.x;
    int wid = tid >> 5;
    int lane = tid & 31;
    int warp_m = wid & 1;
    int warp_n = wid >> 1;
    int r = lane >> 2;
    int c = lane & 3;
    int sub = lane >> 3;
    int rin = lane & 7;
    int n0 = blockIdx.x * 128;
    int m0 = blockIdx.y * 128;

    uint32_t sbase = (uint32_t)__cvta_generic_to_shared(smh);

    const __half* Wt;
    const float* bias;
    const __half* Ain;
    int zsel = 0;
    if (MODE == 0) {
        zsel = blockIdx.z;
        Wt = g_wth + (size_t)zsel * DD * DD;
        bias = (zsel == 0) ? b0 : (zsel == 1) ? b1 : b2;
        Ain = g_xh;
    } else {
        Wt = g_wth + (size_t)3 * DD * DD;
        bias = b0;
        Ain = g_oh;
    }

    auto load_stage = [&](int st, int kt) {
#pragma unroll
        for (int i = 0; i < 4; i++) {
            int idx = tid + i * 256;
            int row = idx >> 3;
            int ch = idx & 7;
            const __half* srcA;
            if (MODE == 0) {
                srcA = Ain + (size_t)(m0 + row) * DD + kt + ch * 8;
            } else {
                int m = m0 + row;
                int b = m >> 11;
                int t = m & 2047;
                int h = kt >> 6;
                srcA = Ain + (((size_t)b * HH + h) * TT + t) * HD + ch * 8;
            }
            cpasync16(&smh[st * TILE_H + row * HSTR + ch * 8], srcA);
            cpasync16(&smh[2 * TILE_H + st * TILE_H + row * HSTR + ch * 8],
                      Wt + (size_t)(n0 + row) * DD + kt + ch * 8);
        }
        CP_COMMIT();
    };

    int a_off = (warp_m * 64 + (sub & 1) * 8 + rin) * HSTR + (sub >> 1) * 8;
    int b_off[2];
#pragma unroll
    for (int j = 0; j < 2; j++)
        b_off[j] = (warp_n * 32 + (2 * j + (sub >> 1)) * 8 + rin) * HSTR
                 + (sub & 1) * 8;

    float acc[4][4][4];
#pragma unroll
    for (int mt = 0; mt < 4; mt++)
#pragma unroll
        for (int nt = 0; nt < 4; nt++)
#pragma unroll
            for (int i = 0; i < 4; i++) acc[mt][nt][i] = 0.f;

    const int NIT = DD / BKH;
    load_stage(0, 0);

    for (int it = 0; it < NIT; it++) {
        CP_WAIT0();
        __syncthreads();

        if (it + 1 < NIT)
            load_stage((it + 1) & 1, (it + 1) * BKH);

        uint32_t aB = sbase + ((it & 1) * TILE_H) * 2;
        uint32_t bB = sbase + (2 * TILE_H + (it & 1) * TILE_H) * 2;
#pragma unroll
        for (int ks = 0; ks < 4; ks++) {
            int k0 = ks * 16;
            uint32_t af[4][4], bf[4][2];
#pragma unroll
            for (int mt = 0; mt < 4; mt++)
                ldsm_x4(af[mt], aB + (a_off + mt * 16 * HSTR + k0) * 2);
#pragma unroll
            for (int j = 0; j < 2; j++) {
                uint32_t t4[4];
                ldsm_x4(t4, bB + (b_off[j] + k0) * 2);
                bf[2 * j][0] = t4[0]; bf[2 * j][1] = t4[1];
                bf[2 * j + 1][0] = t4[2]; bf[2 * j + 1][1] = t4[3];
            }
#pragma unroll
            for (int mt = 0; mt < 4; mt++)
#pragma unroll
                for (int nt = 0; nt < 4; nt++)
                    mma_f16(acc[mt][nt], af[mt], bf[nt]);
        }
    }

#pragma unroll
    for (int nt = 0; nt < 4; nt++) {
        int col = n0 + warp_n * 32 + nt * 8 + c * 2;
        float bx = __ldg(&bias[col]);
        float by = __ldg(&bias[col + 1]);
#pragma unroll
        for (int mt = 0; mt < 4; mt++) {
            int row0 = m0 + warp_m * 64 + mt * 16 + r;
            if (MODE == 0) {
                float e0 = acc[mt][nt][0] + bx;
                float e1 = acc[mt][nt][1] + by;
                float e2 = acc[mt][nt][2] + bx;
                float e3 = acc[mt][nt][3] + by;
                if (zsel == 0) {
                    e0 *= QSCALE; e1 *= QSCALE; e2 *= QSCALE; e3 *= QSCALE;
                }
                __half2 h0 = __floats2half2_rn(e0, e1);
                __half2 h1 = __floats2half2_rn(e2, e3);
                int head = col >> 6;
                int d = col & 63;
                int b = row0 >> 11;
                int t = row0 & 2047;
                if (zsel == 2) {
                    __half* vt = g_vth + (((size_t)b * HH + head) * HD) * TT;
                    vt[(size_t)d * TT + t]           = __low2half(h0);
                    vt[(size_t)(d + 1) * TT + t]     = __high2half(h0);
                    vt[(size_t)d * TT + t + 8]       = __low2half(h1);
                    vt[(size_t)(d + 1) * TT + t + 8] = __high2half(h1);
                } else {
                    __half* out = (zsel == 0) ? g_qh : g_kh;
                    size_t base = (((size_t)b * HH + head) * TT + t) * HD + d;
                    *(__half2*)&out[base] = h0;
                    *(__half2*)&out[base + 8 * HD] = h1;
                }
            } else {
                float2 v0, v1;
                v0.x = acc[mt][nt][0] + bx;
                v0.y = acc[mt][nt][1] + by;
                v1.x = acc[mt][nt][2] + bx;
                v1.y = acc[mt][nt][3] + by;
                *(float2*)&OutDirect[(size_t)row0 * DD + col] = v0;
                *(float2*)&OutDirect[(size_t)(row0 + 8) * DD + col] = v1;
            }
        }
    }
}

// ---------------------------------------------------------------------------
// fp16 flash attention; exp2-domain scores, f16x2 MUFU softmax.
// 128-key supertiles (double-buffered) processed as two 64-key halves:
// half the barriers/commits of 64-key tiling.
// Smem (halves): sQ 9216 | sK[2] 2x9216 (stride 72) | sV[2] 2x8704 (stride 136)
//   = 45056 halves = 90112 B. 2 CTAs/SM.
// ---------------------------------------------------------------------------
#define VSTR 136

__global__ __launch_bounds__(256, 2) void attn_fa()
{
    extern __shared__ __half sa[];

    int bh = blockIdx.y;
    int qt = gridDim.x - 1 - blockIdx.x;   // LPT: heavy blocks first
    int m0 = qt * 128;
    int tid = threadIdx.x;
    int wid = tid >> 5;
    int lane = tid & 31;
    int r = lane >> 2;
    int c = lane & 3;
    int sub = lane >> 3;
    int rin = lane & 7;

    uint32_t sbase = (uint32_t)__cvta_generic_to_shared(sa);

    const __half* Qb  = g_qh + (size_t)bh * TT * HD;
    const __half* Kb  = g_kh + (size_t)bh * TT * HD;
    const __half* Vtb = g_vth + (size_t)bh * HD * TT;
    __half* Ob        = g_oh + (size_t)bh * TT * HD;

    const int NTS = qt + 1;   // 128-key supertiles

    // prefetch supertile 0: K 128x64 (stride 72), V 64x128 (stride 136)
#pragma unroll
    for (int i = 0; i < 4; i++) {
        int idx = tid + i * 256;           // 0..1023
        int krow = idx >> 3;               // 0..127
        int kch = idx & 7;
        cpasync16(&sa[9216 + krow * HSTR + kch * 8],
                  Kb + (size_t)krow * HD + kch * 8);
        int vrow = idx >> 4;               // 0..63
        int vch = idx & 15;
        cpasync16(&sa[27648 + vrow * VSTR + vch * 8],
                  Vtb + (size_t)vrow * TT + vch * 8);
    }
    CP_COMMIT();

    // Q tile -> smem
#pragma unroll
    for (int i = 0; i < 4; i++) {
        int idx = tid + i * 256;
        int row = idx >> 3;
        int ch = idx & 7;
        *(uint4*)&sa[row * HSTR + ch * 8] =
            *(const uint4*)&Qb[(size_t)(m0 + row) * HD + ch * 8];
    }
    __syncthreads();

    int lr = wid * 16 + r;
    int q_off = (wid * 16 + (sub & 1) * 8 + rin) * HSTR + (sub >> 1) * 8;
    int k_off[4], v_off[4];
#pragma unroll
    for (int j = 0; j < 4; j++) {
        k_off[j] = ((2 * j + (sub >> 1)) * 8 + rin) * HSTR + (sub & 1) * 8;
        v_off[j] = ((2 * j + (sub >> 1)) * 8 + rin) * VSTR + (sub & 1) * 8;
    }

    uint32_t qf[4][4];
#pragma unroll
    for (int kc = 0; kc < 4; kc++)
        ldsm_x4(qf[kc], sbase + (q_off + kc * 16) * 2);

    float o[8][4];
#pragma unroll
    for (int nt = 0; nt < 8; nt++)
#pragma unroll
        for (int i = 0; i < 4; i++) o[nt][i] = 0.f;

    float mr0 = -INFINITY, mr1 = -INFINITY;
    float l0 = 0.f, l1 = 0.f;
    int rg0 = m0 + lr;
    int rg1 = rg0 + 8;

    for (int s = 0; s < NTS; s++) {
        CP_WAIT0();
        __syncthreads();

        if (s + 1 < NTS) {
            int kt2 = (s + 1) * 128;
            int st2 = (s + 1) & 1;
#pragma unroll
            for (int i = 0; i < 4; i++) {
                int idx = tid + i * 256;
                int krow = idx >> 3;
                int kch = idx & 7;
                cpasync16(&sa[9216 + st2 * 9216 + krow * HSTR + kch * 8],
                          Kb + (size_t)(kt2 + krow) * HD + kch * 8);
                int vrow = idx >> 4;
                int vch = idx & 15;
                cpasync16(&sa[27648 + st2 * 8704 + vrow * VSTR + vch * 8],
                          Vtb + (size_t)vrow * TT + kt2 + vch * 8);
            }
            CP_COMMIT();
        }

        uint32_t kBase = sbase + (9216 + (s & 1) * 9216) * 2;
        uint32_t vBase = sbase + (27648 + (s & 1) * 8704) * 2;

#pragma unroll
        for (int h = 0; h < 2; h++) {
            int kth = s * 128 + h * 64;
            uint32_t kB = kBase + (h * 64 * HSTR) * 2;   // key-row offset
            uint32_t vB = vBase + (h * 64) * 2;          // key-col offset

            // ---- S = Q K^T (exp2-domain) ----
            float sc[8][4];
#pragma unroll
            for (int nt = 0; nt < 8; nt++)
#pragma unroll
                for (int i = 0; i < 4; i++) sc[nt][i] = 0.f;
#pragma unroll
            for (int kc = 0; kc < 4; kc++) {
#pragma unroll
                for (int j = 0; j < 4; j++) {
                    uint32_t t4[4];
                    ldsm_x4(t4, kB + (k_off[j] + kc * 16) * 2);
                    mma_f16(sc[2 * j],     qf[kc], t4);
                    mma_f16(sc[2 * j + 1], qf[kc], t4 + 2);
                }
            }

            // ---- mask + online softmax (f16x2 MUFU) ----
            bool need_mask = (kth + 63 > m0);
            float mx0 = mr0, mx1 = mr1;
#pragma unroll
            for (int nt = 0; nt < 8; nt++) {
                float* sv = sc[nt];
                if (need_mask) {
                    int col0 = kth + nt * 8 + 2 * c;
                    if (col0     > rg0) sv[0] = -INFINITY;
                    if (col0 + 1 > rg0) sv[1] = -INFINITY;
                    if (col0     > rg1) sv[2] = -INFINITY;
                    if (col0 + 1 > rg1) sv[3] = -INFINITY;
                }
                mx0 = fmaxf(mx0, fmaxf(sv[0], sv[1]));
                mx1 = fmaxf(mx1, fmaxf(sv[2], sv[3]));
            }
            mx0 = fmaxf(mx0, __shfl_xor_sync(0xffffffffu, mx0, 1));
            mx0 = fmaxf(mx0, __shfl_xor_sync(0xffffffffu, mx0, 2));
            mx1 = fmaxf(mx1, __shfl_xor_sync(0xffffffffu, mx1, 1));
            mx1 = fmaxf(mx1, __shfl_xor_sync(0xffffffffu, mx1, 2));

            float a0 = ex2(mr0 - mx0);
            float a1 = ex2(mr1 - mx1);
            float sum0 = 0.f, sum1 = 0.f;
            uint32_t pk[8][2];
#pragma unroll
            for (int nt = 0; nt < 8; nt++) {
                __half2 d01 = __floats2half2_rn(sc[nt][0] - mx0,
                                                sc[nt][1] - mx0);
                __half2 d23 = __floats2half2_rn(sc[nt][2] - mx1,
                                                sc[nt][3] - mx1);
                pk[nt][0] = ex2_h2(*(uint32_t*)&d01);
                pk[nt][1] = ex2_h2(*(uint32_t*)&d23);
                float2 f01 = __half22float2(*(__half2*)&pk[nt][0]);
                float2 f23 = __half22float2(*(__half2*)&pk[nt][1]);
                sum0 += f01.x + f01.y;
                sum1 += f23.x + f23.y;
            }
            sum0 += __shfl_xor_sync(0xffffffffu, sum0, 1);
            sum0 += __shfl_xor_sync(0xffffffffu, sum0, 2);
            sum1 += __shfl_xor_sync(0xffffffffu, sum1, 1);
            sum1 += __shfl_xor_sync(0xffffffffu, sum1, 2);
            l0 = l0 * a0 + sum0;
            l1 = l1 * a1 + sum1;
#pragma unroll
            for (int nt = 0; nt < 8; nt++) {
                o[nt][0] *= a0; o[nt][1] *= a0;
                o[nt][2] *= a1; o[nt][3] *= a1;
            }
            mr0 = mx0; mr1 = mx1;

            // ---- O += P V ----
#pragma unroll
            for (int kc = 0; kc < 4; kc++) {
                uint32_t af[4];
                af[0] = pk[2 * kc][0];
                af[1] = pk[2 * kc][1];
                af[2] = pk[2 * kc + 1][0];
                af[3] = pk[2 * kc + 1][1];
#pragma unroll
                for (int j = 0; j < 4; j++) {
                    uint32_t t4[4];
                    ldsm_x4(t4, vB + (v_off[j] + kc * 16) * 2);
                    mma_f16(o[2 * j],     af, t4);
                    mma_f16(o[2 * j + 1], af, t4 + 2);
                }
            }
        }
    }

    float i0 = 1.f / l0, i1 = 1.f / l1;
#pragma unroll
    for (int nt = 0; nt < 8; nt++) {
        *(__half2*)&Ob[(size_t)rg0 * HD + nt * 8 + 2 * c] =
            __floats2half2_rn(o[nt][0] * i0, o[nt][1] * i0);
        *(__half2*)&Ob[(size_t)rg1 * HD + nt * 8 + 2 * c] =
            __floats2half2_rn(o[nt][2] * i1, o[nt][3] * i1);
    }
}

extern "C" void kernel_launch(void* const* d_in, const int* in_sizes, int n_in,
                              void* d_out, int out_size)
{
    const float* x  = (const float*)d_in[0];
    const float* Wq = (const float*)d_in[1];
    const float* bq = (const float*)d_in[2];
    const float* Wk = (const float*)d_in[3];
    const float* bk = (const float*)d_in[4];
    const float* Wv = (const float*)d_in[5];
    const float* bv = (const float*)d_in[6];
    const float* Wo = (const float*)d_in[7];
    const float* bo = (const float*)d_in[8];
    float* out = (float*)d_out;

    const int GEMM_SMEM = 4 * TILE_H * 2;   // 73728 B
    const int ATTN_SMEM = 45056 * 2;        // 90112 B
    cudaFuncSetAttribute(gemm_tc<0>, cudaFuncAttributeMaxDynamicSharedMemorySize,
                         GEMM_SMEM);
    cudaFuncSetAttribute(gemm_tc<1>, cudaFuncAttributeMaxDynamicSharedMemorySize,
                         GEMM_SMEM);
    cudaFuncSetAttribute(attn_fa, cudaFuncAttributeMaxDynamicSharedMemorySize,
                         ATTN_SMEM);

    round_x<<<(BB * TT * DD) / (256 * 4), 256>>>(x);

    dim3 gt(32, 32, 4);
    transpose_w<<<gt, dim3(32, 8)>>>(Wq, Wk, Wv, Wo);

    dim3 g1(DD / 128, (BB * TT) / 128, 3);
    gemm_tc<0><<<g1, 256, GEMM_SMEM>>>(bq, bk, bv, nullptr);

    dim3 g2(TT / 128, BB * HH);
    attn_fa<<<g2, 256, ATTN_SMEM>>>();

    dim3 g3(DD / 128, (BB * TT) / 128);
    gemm_tc<1><<<g3, 256, GEMM_SMEM>>>(bo, nullptr, nullptr, out);
}

// round 15
// speedup vs baseline: 2.2538x; 1.0052x over previous
#include <cuda_runtime.h>
#include <cuda_fp16.h>
#include <math.h>
#include <stdint.h>

#define BB 4
#define TT 2048
#define DD 1024
#define HH 16
#define HD 64
#define SCALE_F 0.125f   // 1/sqrt(64)
#define QSCALE (SCALE_F * 1.44269504088896f)   // fold log2(e): exp2-domain scores

// fp16 scratch. g_qh (PRE-SCALED by QSCALE), g_kh, g_oh: [B, H, T, hd].
// g_vth: [B, H, hd, T].
__device__ __half g_qh[(size_t)BB * HH * TT * HD];
__device__ __half g_kh[(size_t)BB * HH * TT * HD];
__device__ __half g_vth[(size_t)BB * HH * TT * HD];
__device__ __half g_oh[(size_t)BB * HH * TT * HD];
__device__ __half g_xh[(size_t)BB * TT * DD];          // fp16 X
__device__ __half g_wth[(size_t)4 * DD * DD];          // W^T [N][K] fp16

__device__ __forceinline__ void mma_f16(float* d, const uint32_t* a,
                                        const uint32_t* b) {
    asm volatile(
        "mma.sync.aligned.m16n8k16.row.col.f32.f16.f16.f32 "
        "{%0,%1,%2,%3}, {%4,%5,%6,%7}, {%8,%9}, {%0,%1,%2,%3};"
        : "+f"(d[0]), "+f"(d[1]), "+f"(d[2]), "+f"(d[3])
        : "r"(a[0]), "r"(a[1]), "r"(a[2]), "r"(a[3]),
          "r"(b[0]), "r"(b[1]));
}

__device__ __forceinline__ void ldsm_x4(uint32_t* d, uint32_t saddr) {
    asm volatile(
        "ldmatrix.sync.aligned.m8n8.x4.shared.b16 {%0,%1,%2,%3}, [%4];"
        : "=r"(d[0]), "=r"(d[1]), "=r"(d[2]), "=r"(d[3]) : "r"(saddr));
}

__device__ __forceinline__ float ex2(float x) {
    float y;
    asm("ex2.approx.f32 %0, %1;" : "=f"(y) : "f"(x));
    return y;
}
__device__ __forceinline__ uint32_t ex2_h2(uint32_t x) {
    uint32_t y;
    asm("ex2.approx.f16x2 %0, %1;" : "=r"(y) : "r"(x));
    return y;
}

__device__ __forceinline__ void cpasync16(void* sptr, const void* gptr) {
    uint32_t sa = (uint32_t)__cvta_generic_to_shared(sptr);
    asm volatile("cp.async.ca.shared.global [%0], [%1], 16;"
                 :: "r"(sa), "l"(gptr));
}
#define CP_COMMIT() asm volatile("cp.async.commit_group;" ::: "memory")
#define CP_WAIT0()  asm volatile("cp.async.wait_group 0;" ::: "memory")
#define CP_WAIT1()  asm volatile("cp.async.wait_group 1;" ::: "memory")

// ---------------------------------------------------------------------------
// X -> fp16
// ---------------------------------------------------------------------------
__global__ __launch_bounds__(256) void round_x(const float* __restrict__ x)
{
    size_t i = ((size_t)blockIdx.x * 256 + threadIdx.x) * 4;
    float4 v = *(const float4*)&x[i];
    __half2 h0 = __floats2half2_rn(v.x, v.y);
    __half2 h1 = __floats2half2_rn(v.z, v.w);
    *(uint2*)&g_xh[i] = make_uint2(*(uint32_t*)&h0, *(uint32_t*)&h1);
}

// ---------------------------------------------------------------------------
// Weight transpose: W [K,N] f32 -> g_wth slice [N,K] fp16
// ---------------------------------------------------------------------------
__global__ __launch_bounds__(256) void transpose_w(
    const float* __restrict__ Wq, const float* __restrict__ Wk,
    const float* __restrict__ Wv, const float* __restrict__ Wo)
{
    const float* src = (blockIdx.z == 0) ? Wq : (blockIdx.z == 1) ? Wk
                     : (blockIdx.z == 2) ? Wv : Wo;
    __half* dst = g_wth + (size_t)blockIdx.z * DD * DD;

    __shared__ float tile[32][33];
    int x = blockIdx.x * 32 + threadIdx.x;
    int y0 = blockIdx.y * 32;
#pragma unroll
    for (int j = threadIdx.y; j < 32; j += 8)
        tile[j][threadIdx.x] = src[(size_t)(y0 + j) * DD + x];
    __syncthreads();
    int x2 = y0 + threadIdx.x;
    int y2 = blockIdx.x * 32;
#pragma unroll
    for (int j = threadIdx.y; j < 32; j += 8)
        dst[(size_t)(y2 + j) * DD + x2] = __float2half_rn(tile[threadIdx.x][j]);
}

// ---------------------------------------------------------------------------
// fp16 cp.async 3-STAGE GEMM, BK=64, swizzled smem (no padding).
// Tile: 128 rows x 64 halves (128B rows). unit' = unit ^ (row&7) on 16B units.
// Smem: 6 tiles x 16KB = 96KB.  Prefetch distance 2.
// MODE 0: A = g_xh; z=0 -> g_qh (scaled by QSCALE), z=1 -> g_kh,
//         z=2 -> g_vth (transposed).
// MODE 1: A = g_oh (gathered), out = d_out f32 [B*T, D].
// ---------------------------------------------------------------------------
#define BKH 64
#define TILE_H 8192            // halves per tile (128 x 64)

template <int MODE>
__global__ __launch_bounds__(256) void gemm_tc(
    const float* __restrict__ b0, const float* __restrict__ b1,
    const float* __restrict__ b2, float* __restrict__ OutDirect)
{
    extern __shared__ __half smh[];
    // A st0|A st1|A st2|B st0|B st1|B st2

    int tid = threadIdx.x;
    int wid = tid >> 5;
    int lane = tid & 31;
    int warp_m = wid & 1;
    int warp_n = wid >> 1;
    int r = lane >> 2;
    int c = lane & 3;
    int sub = lane >> 3;
    int rin = lane & 7;
    int n0 = blockIdx.x * 128;
    int m0 = blockIdx.y * 128;

    uint32_t sbase = (uint32_t)__cvta_generic_to_shared(smh);

    const __half* Wt;
    const float* bias;
    const __half* Ain;
    int zsel = 0;
    if (MODE == 0) {
        zsel = blockIdx.z;
        Wt = g_wth + (size_t)zsel * DD * DD;
        bias = (zsel == 0) ? b0 : (zsel == 1) ? b1 : b2;
        Ain = g_xh;
    } else {
        Wt = g_wth + (size_t)3 * DD * DD;
        bias = b0;
        Ain = g_oh;
    }

    auto load_stage = [&](int st, int kt) {
#pragma unroll
        for (int i = 0; i < 4; i++) {
            int idx = tid + i * 256;        // 0..1023
            int row = idx >> 3;             // 0..127
            int ch = idx & 7;               // 16B unit
            int swu = ch ^ (row & 7);       // swizzled unit
            const __half* srcA;
            if (MODE == 0) {
                srcA = Ain + (size_t)(m0 + row) * DD + kt + ch * 8;
            } else {
                int m = m0 + row;
                int b = m >> 11;
                int t = m & 2047;
                int h = kt >> 6;
                srcA = Ain + (((size_t)b * HH + h) * TT + t) * HD + ch * 8;
            }
            cpasync16(&smh[st * TILE_H + row * 64 + swu * 8], srcA);
            cpasync16(&smh[(3 + st) * TILE_H + row * 64 + swu * 8],
                      Wt + (size_t)(n0 + row) * DD + kt + ch * 8);
        }
        CP_COMMIT();
    };

    // precomputed per-thread ldmatrix row info
    // A: 4 m-frags, row = warp_m*64 + mt*16 + (sub&1)*8 + rin, unit = 2ks + (sub>>1)
    uint32_t a_rb[4];   // byte offset of row*64 halves
    uint32_t a_r7[4];
#pragma unroll
    for (int mt = 0; mt < 4; mt++) {
        int row = warp_m * 64 + mt * 16 + (sub & 1) * 8 + rin;
        a_rb[mt] = (uint32_t)row * 128;     // row*64 halves * 2B
        a_r7[mt] = (uint32_t)(row & 7);
    }
    int a_usub = sub >> 1;
    // B: 2 ldsm covering 4 n-frags; row = warp_n*32 + (2j+(sub>>1))*8 + rin,
    // unit = 2ks + (sub&1)
    uint32_t b_rb[2], b_r7[2];
#pragma unroll
    for (int j = 0; j < 2; j++) {
        int row = warp_n * 32 + (2 * j + (sub >> 1)) * 8 + rin;
        b_rb[j] = (uint32_t)row * 128;
        b_r7[j] = (uint32_t)(row & 7);
    }
    int b_usub = sub & 1;

    float acc[4][4][4];
#pragma unroll
    for (int mt = 0; mt < 4; mt++)
#pragma unroll
        for (int nt = 0; nt < 4; nt++)
#pragma unroll
            for (int i = 0; i < 4; i++) acc[mt][nt][i] = 0.f;

    const int NIT = DD / BKH;   // 16
    load_stage(0, 0);
    load_stage(1, BKH);

    for (int it = 0; it < NIT; it++) {
        if (it + 1 < NIT) { CP_WAIT1(); } else { CP_WAIT0(); }
        __syncthreads();

        if (it + 2 < NIT)
            load_stage((it + 2) % 3, (it + 2) * BKH);

        int st = it % 3;
        uint32_t aB = sbase + st * (TILE_H * 2);
        uint32_t bB = sbase + (3 + st) * (TILE_H * 2);
#pragma unroll
        for (int ks = 0; ks < 4; ks++) {
            uint32_t af[4][4], bf[4][2];
#pragma unroll
            for (int mt = 0; mt < 4; mt++) {
                uint32_t u = (uint32_t)(2 * ks + a_usub) ^ a_r7[mt];
                ldsm_x4(af[mt], aB + a_rb[mt] + (u << 4));
            }
#pragma unroll
            for (int j = 0; j < 2; j++) {
                uint32_t u = (uint32_t)(2 * ks + b_usub) ^ b_r7[j];
                uint32_t t4[4];
                ldsm_x4(t4, bB + b_rb[j] + (u << 4));
                bf[2 * j][0] = t4[0]; bf[2 * j][1] = t4[1];
                bf[2 * j + 1][0] = t4[2]; bf[2 * j + 1][1] = t4[3];
            }
#pragma unroll
            for (int mt = 0; mt < 4; mt++)
#pragma unroll
                for (int nt = 0; nt < 4; nt++)
                    mma_f16(acc[mt][nt], af[mt], bf[nt]);
        }
    }

#pragma unroll
    for (int nt = 0; nt < 4; nt++) {
        int col = n0 + warp_n * 32 + nt * 8 + c * 2;
        float bx = __ldg(&bias[col]);
        float by = __ldg(&bias[col + 1]);
#pragma unroll
        for (int mt = 0; mt < 4; mt++) {
            int row0 = m0 + warp_m * 64 + mt * 16 + r;
            if (MODE == 0) {
                float e0 = acc[mt][nt][0] + bx;
                float e1 = acc[mt][nt][1] + by;
                float e2 = acc[mt][nt][2] + bx;
                float e3 = acc[mt][nt][3] + by;
                if (zsel == 0) {
                    e0 *= QSCALE; e1 *= QSCALE; e2 *= QSCALE; e3 *= QSCALE;
                }
                __half2 h0 = __floats2half2_rn(e0, e1);
                __half2 h1 = __floats2half2_rn(e2, e3);
                int head = col >> 6;
                int d = col & 63;
                int b = row0 >> 11;
                int t = row0 & 2047;
                if (zsel == 2) {
                    __half* vt = g_vth + (((size_t)b * HH + head) * HD) * TT;
                    vt[(size_t)d * TT + t]           = __low2half(h0);
                    vt[(size_t)(d + 1) * TT + t]     = __high2half(h0);
                    vt[(size_t)d * TT + t + 8]       = __low2half(h1);
                    vt[(size_t)(d + 1) * TT + t + 8] = __high2half(h1);
                } else {
                    __half* out = (zsel == 0) ? g_qh : g_kh;
                    size_t base = (((size_t)b * HH + head) * TT + t) * HD + d;
                    *(__half2*)&out[base] = h0;
                    *(__half2*)&out[base + 8 * HD] = h1;
                }
            } else {
                float2 v0, v1;
                v0.x = acc[mt][nt][0] + bx;
                v0.y = acc[mt][nt][1] + by;
                v1.x = acc[mt][nt][2] + bx;
                v1.y = acc[mt][nt][3] + by;
                *(float2*)&OutDirect[(size_t)row0 * DD + col] = v0;
                *(float2*)&OutDirect[(size_t)(row0 + 8) * DD + col] = v1;
            }
        }
    }
}

// ---------------------------------------------------------------------------
// fp16 flash attention (unchanged from round 14).
// ---------------------------------------------------------------------------
#define HSTR 72
#define VSTR 136

__global__ __launch_bounds__(256, 2) void attn_fa()
{
    extern __shared__ __half sa[];

    int bh = blockIdx.y;
    int qt = gridDim.x - 1 - blockIdx.x;   // LPT
    int m0 = qt * 128;
    int tid = threadIdx.x;
    int wid = tid >> 5;
    int lane = tid & 31;
    int r = lane >> 2;
    int c = lane & 3;
    int sub = lane >> 3;
    int rin = lane & 7;

    uint32_t sbase = (uint32_t)__cvta_generic_to_shared(sa);

    const __half* Qb  = g_qh + (size_t)bh * TT * HD;
    const __half* Kb  = g_kh + (size_t)bh * TT * HD;
    const __half* Vtb = g_vth + (size_t)bh * HD * TT;
    __half* Ob        = g_oh + (size_t)bh * TT * HD;

    const int NTS = qt + 1;

#pragma unroll
    for (int i = 0; i < 4; i++) {
        int idx = tid + i * 256;
        int krow = idx >> 3;
        int kch = idx & 7;
        cpasync16(&sa[9216 + krow * HSTR + kch * 8],
                  Kb + (size_t)krow * HD + kch * 8);
        int vrow = idx >> 4;
        int vch = idx & 15;
        cpasync16(&sa[27648 + vrow * VSTR + vch * 8],
                  Vtb + (size_t)vrow * TT + vch * 8);
    }
    CP_COMMIT();

#pragma unroll
    for (int i = 0; i < 4; i++) {
        int idx = tid + i * 256;
        int row = idx >> 3;
        int ch = idx & 7;
        *(uint4*)&sa[row * HSTR + ch * 8] =
            *(const uint4*)&Qb[(size_t)(m0 + row) * HD + ch * 8];
    }
    __syncthreads();

    int lr = wid * 16 + r;
    int q_off = (wid * 16 + (sub & 1) * 8 + rin) * HSTR + (sub >> 1) * 8;
    int k_off[4], v_off[4];
#pragma unroll
    for (int j = 0; j < 4; j++) {
        k_off[j] = ((2 * j + (sub >> 1)) * 8 + rin) * HSTR + (sub & 1) * 8;
        v_off[j] = ((2 * j + (sub >> 1)) * 8 + rin) * VSTR + (sub & 1) * 8;
    }

    uint32_t qf[4][4];
#pragma unroll
    for (int kc = 0; kc < 4; kc++)
        ldsm_x4(qf[kc], sbase + (q_off + kc * 16) * 2);

    float o[8][4];
#pragma unroll
    for (int nt = 0; nt < 8; nt++)
#pragma unroll
        for (int i = 0; i < 4; i++) o[nt][i] = 0.f;

    float mr0 = -INFINITY, mr1 = -INFINITY;
    float l0 = 0.f, l1 = 0.f;
    int rg0 = m0 + lr;
    int rg1 = rg0 + 8;

    for (int s = 0; s < NTS; s++) {
        CP_WAIT0();
        __syncthreads();

        if (s + 1 < NTS) {
            int kt2 = (s + 1) * 128;
            int st2 = (s + 1) & 1;
#pragma unroll
            for (int i = 0; i < 4; i++) {
                int idx = tid + i * 256;
                int krow = idx >> 3;
                int kch = idx & 7;
                cpasync16(&sa[9216 + st2 * 9216 + krow * HSTR + kch * 8],
                          Kb + (size_t)(kt2 + krow) * HD + kch * 8);
                int vrow = idx >> 4;
                int vch = idx & 15;
                cpasync16(&sa[27648 + st2 * 8704 + vrow * VSTR + vch * 8],
                          Vtb + (size_t)vrow * TT + kt2 + vch * 8);
            }
            CP_COMMIT();
        }

        uint32_t kBase = sbase + (9216 + (s & 1) * 9216) * 2;
        uint32_t vBase = sbase + (27648 + (s & 1) * 8704) * 2;

#pragma unroll
        for (int h = 0; h < 2; h++) {
            int kth = s * 128 + h * 64;
            uint32_t kB = kBase + (h * 64 * HSTR) * 2;
            uint32_t vB = vBase + (h * 64) * 2;

            float sc[8][4];
#pragma unroll
            for (int nt = 0; nt < 8; nt++)
#pragma unroll
                for (int i = 0; i < 4; i++) sc[nt][i] = 0.f;
#pragma unroll
            for (int kc = 0; kc < 4; kc++) {
#pragma unroll
                for (int j = 0; j < 4; j++) {
                    uint32_t t4[4];
                    ldsm_x4(t4, kB + (k_off[j] + kc * 16) * 2);
                    mma_f16(sc[2 * j],     qf[kc], t4);
                    mma_f16(sc[2 * j + 1], qf[kc], t4 + 2);
                }
            }

            bool need_mask = (kth + 63 > m0);
            float mx0 = mr0, mx1 = mr1;
#pragma unroll
            for (int nt = 0; nt < 8; nt++) {
                float* sv = sc[nt];
                if (need_mask) {
                    int col0 = kth + nt * 8 + 2 * c;
                    if (col0     > rg0) sv[0] = -INFINITY;
                    if (col0 + 1 > rg0) sv[1] = -INFINITY;
                    if (col0     > rg1) sv[2] = -INFINITY;
                    if (col0 + 1 > rg1) sv[3] = -INFINITY;
                }
                mx0 = fmaxf(mx0, fmaxf(sv[0], sv[1]));
                mx1 = fmaxf(mx1, fmaxf(sv[2], sv[3]));
            }
            mx0 = fmaxf(mx0, __shfl_xor_sync(0xffffffffu, mx0, 1));
            mx0 = fmaxf(mx0, __shfl_xor_sync(0xffffffffu, mx0, 2));
            mx1 = fmaxf(mx1, __shfl_xor_sync(0xffffffffu, mx1, 1));
            mx1 = fmaxf(mx1, __shfl_xor_sync(0xffffffffu, mx1, 2));

            float a0 = ex2(mr0 - mx0);
            float a1 = ex2(mr1 - mx1);
            float sum0 = 0.f, sum1 = 0.f;
            uint32_t pk[8][2];
#pragma unroll
            for (int nt = 0; nt < 8; nt++) {
                __half2 d01 = __floats2half2_rn(sc[nt][0] - mx0,
                                                sc[nt][1] - mx0);
                __half2 d23 = __floats2half2_rn(sc[nt][2] - mx1,
                                                sc[nt][3] - mx1);
                pk[nt][0] = ex2_h2(*(uint32_t*)&d01);
                pk[nt][1] = ex2_h2(*(uint32_t*)&d23);
                float2 f01 = __half22float2(*(__half2*)&pk[nt][0]);
                float2 f23 = __half22float2(*(__half2*)&pk[nt][1]);
                sum0 += f01.x + f01.y;
                sum1 += f23.x + f23.y;
            }
            sum0 += __shfl_xor_sync(0xffffffffu, sum0, 1);
            sum0 += __shfl_xor_sync(0xffffffffu, sum0, 2);
            sum1 += __shfl_xor_sync(0xffffffffu, sum1, 1);
            sum1 += __shfl_xor_sync(0xffffffffu, sum1, 2);
            l0 = l0 * a0 + sum0;
            l1 = l1 * a1 + sum1;
#pragma unroll
            for (int nt = 0; nt < 8; nt++) {
                o[nt][0] *= a0; o[nt][1] *= a0;
                o[nt][2] *= a1; o[nt][3] *= a1;
            }
            mr0 = mx0; mr1 = mx1;

#pragma unroll
            for (int kc = 0; kc < 4; kc++) {
                uint32_t af[4];
                af[0] = pk[2 * kc][0];
                af[1] = pk[2 * kc][1];
                af[2] = pk[2 * kc + 1][0];
                af[3] = pk[2 * kc + 1][1];
#pragma unroll
                for (int j = 0; j < 4; j++) {
                    uint32_t t4[4];
                    ldsm_x4(t4, vB + (v_off[j] + kc * 16) * 2);
                    mma_f16(o[2 * j],     af, t4);
                    mma_f16(o[2 * j + 1], af, t4 + 2);
                }
            }
        }
    }

    float i0 = 1.f / l0, i1 = 1.f / l1;
#pragma unroll
    for (int nt = 0; nt < 8; nt++) {
        *(__half2*)&Ob[(size_t)rg0 * HD + nt * 8 + 2 * c] =
            __floats2half2_rn(o[nt][0] * i0, o[nt][1] * i0);
        *(__half2*)&Ob[(size_t)rg1 * HD + nt * 8 + 2 * c] =
            __floats2half2_rn(o[nt][2] * i1, o[nt][3] * i1);
    }
}

extern "C" void kernel_launch(void* const* d_in, const int* in_sizes, int n_in,
                              void* d_out, int out_size)
{
    const float* x  = (const float*)d_in[0];
    const float* Wq = (const float*)d_in[1];
    const float* bq = (const float*)d_in[2];
    const float* Wk = (const float*)d_in[3];
    const float* bk = (const float*)d_in[4];
    const float* Wv = (const float*)d_in[5];
    const float* bv = (const float*)d_in[6];
    const float* Wo = (const float*)d_in[7];
    const float* bo = (const float*)d_in[8];
    float* out = (float*)d_out;

    const int GEMM_SMEM = 6 * TILE_H * 2;   // 98304 B
    const int ATTN_SMEM = 45056 * 2;        // 90112 B
    cudaFuncSetAttribute(gemm_tc<0>, cudaFuncAttributeMaxDynamicSharedMemorySize,
                         GEMM_SMEM);
    cudaFuncSetAttribute(gemm_tc<1>, cudaFuncAttributeMaxDynamicSharedMemorySize,
                         GEMM_SMEM);
    cudaFuncSetAttribute(attn_fa, cudaFuncAttributeMaxDynamicSharedMemorySize,
                         ATTN_SMEM);

    round_x<<<(BB * TT * DD) / (256 * 4), 256>>>(x);

    dim3 gt(32, 32, 4);
    transpose_w<<<gt, dim3(32, 8)>>>(Wq, Wk, Wv, Wo);

    dim3 g1(DD / 128, (BB * TT) / 128, 3);
    gemm_tc<0><<<g1, 256, GEMM_SMEM>>>(bq, bk, bv, nullptr);

    dim3 g2(TT / 128, BB * HH);
    attn_fa<<<g2, 256, ATTN_SMEM>>>();

    dim3 g3(DD / 128, (BB * TT) / 128);
    gemm_tc<1><<<g3, 256, GEMM_SMEM>>>(bo, nullptr, nullptr, out);
}

// round 16
// speedup vs baseline: 2.3023x; 1.0215x over previous
#include <cuda_runtime.h>
#include <cuda_fp16.h>
#include <math.h>
#include <stdint.h>

#define BB 4
#define TT 2048
#define DD 1024
#define HH 16
#define HD 64
#define SCALE_F 0.125f   // 1/sqrt(64)
#define QSCALE (SCALE_F * 1.44269504088896f)   // fold log2(e): exp2-domain scores

// fp16 scratch. g_qh (PRE-SCALED by QSCALE), g_kh: [B, H, T, hd].
// g_vth: [B, H, hd, T].  g_oh: [B*T, D]  (attention output, GEMM-ready).
__device__ __half g_qh[(size_t)BB * HH * TT * HD];
__device__ __half g_kh[(size_t)BB * HH * TT * HD];
__device__ __half g_vth[(size_t)BB * HH * TT * HD];
__device__ __half g_oh[(size_t)BB * TT * DD];
__device__ __half g_xh[(size_t)BB * TT * DD];          // fp16 X
__device__ __half g_wth[(size_t)4 * DD * DD];          // W^T [N][K] fp16

__device__ __forceinline__ void mma_f16(float* d, const uint32_t* a,
                                        const uint32_t* b) {
    asm volatile(
        "mma.sync.aligned.m16n8k16.row.col.f32.f16.f16.f32 "
        "{%0,%1,%2,%3}, {%4,%5,%6,%7}, {%8,%9}, {%0,%1,%2,%3};"
        : "+f"(d[0]), "+f"(d[1]), "+f"(d[2]), "+f"(d[3])
        : "r"(a[0]), "r"(a[1]), "r"(a[2]), "r"(a[3]),
          "r"(b[0]), "r"(b[1]));
}

__device__ __forceinline__ void ldsm_x4(uint32_t* d, uint32_t saddr) {
    asm volatile(
        "ldmatrix.sync.aligned.m8n8.x4.shared.b16 {%0,%1,%2,%3}, [%4];"
        : "=r"(d[0]), "=r"(d[1]), "=r"(d[2]), "=r"(d[3]) : "r"(saddr));
}

__device__ __forceinline__ float ex2(float x) {
    float y;
    asm("ex2.approx.f32 %0, %1;" : "=f"(y) : "f"(x));
    return y;
}
__device__ __forceinline__ uint32_t ex2_h2(uint32_t x) {
    uint32_t y;
    asm("ex2.approx.f16x2 %0, %1;" : "=r"(y) : "r"(x));
    return y;
}

__device__ __forceinline__ void cpasync16(void* sptr, const void* gptr) {
    uint32_t sa = (uint32_t)__cvta_generic_to_shared(sptr);
    asm volatile("cp.async.ca.shared.global [%0], [%1], 16;"
                 :: "r"(sa), "l"(gptr));
}
#define CP_COMMIT() asm volatile("cp.async.commit_group;" ::: "memory")
#define CP_WAIT0()  asm volatile("cp.async.wait_group 0;" ::: "memory")
#define CP_WAIT1()  asm volatile("cp.async.wait_group 1;" ::: "memory")

// ---------------------------------------------------------------------------
// Fused prep: blocks [0, 8192) convert X -> fp16;
// blocks [8192, 12288) transpose+convert W -> g_wth [N][K].
// ---------------------------------------------------------------------------
__global__ __launch_bounds__(256) void prep(
    const float* __restrict__ x,
    const float* __restrict__ Wq, const float* __restrict__ Wk,
    const float* __restrict__ Wv, const float* __restrict__ Wo)
{
    __shared__ float tile[32][33];
    int blk = blockIdx.x;
    int tid = threadIdx.x;
    if (blk < 8192) {
        size_t i = ((size_t)blk * 256 + tid) * 4;
        float4 v = *(const float4*)&x[i];
        __half2 h0 = __floats2half2_rn(v.x, v.y);
        __half2 h1 = __floats2half2_rn(v.z, v.w);
        *(uint2*)&g_xh[i] = make_uint2(*(uint32_t*)&h0, *(uint32_t*)&h1);
    } else {
        int wb = blk - 8192;             // 0..4095
        int z = wb >> 10;                // matrix
        int t = wb & 1023;               // 32x32 tile index
        int bx = t & 31, by = t >> 5;
        const float* src = (z == 0) ? Wq : (z == 1) ? Wk : (z == 2) ? Wv : Wo;
        __half* dst = g_wth + (size_t)z * DD * DD;
        int tx = tid & 31, ty = tid >> 5;     // 32 x 8
        int xg = bx * 32 + tx;
        int y0 = by * 32;
#pragma unroll
        for (int j = ty; j < 32; j += 8)
            tile[j][tx] = src[(size_t)(y0 + j) * DD + xg];
        __syncthreads();
        int x2 = y0 + tx;
        int y2 = bx * 32;
#pragma unroll
        for (int j = ty; j < 32; j += 8)
            dst[(size_t)(y2 + j) * DD + x2] = __float2half_rn(tile[tx][j]);
    }
}

// ---------------------------------------------------------------------------
// fp16 cp.async 3-STAGE GEMM, BK=64, swizzled smem.
// MODE 0: A = g_xh; z=0 -> g_qh (scaled), z=1 -> g_kh, z=2 -> g_vth (trans).
// MODE 1: A = g_oh [B*T, D] (LINEAR, same as MODE 0), out = d_out f32.
// ---------------------------------------------------------------------------
#define BKH 64
#define TILE_H 8192            // halves per tile (128 x 64)

template <int MODE>
__global__ __launch_bounds__(256) void gemm_tc(
    const float* __restrict__ b0, const float* __restrict__ b1,
    const float* __restrict__ b2, float* __restrict__ OutDirect)
{
    extern __shared__ __half smh[];

    int tid = threadIdx.x;
    int wid = tid >> 5;
    int lane = tid & 31;
    int warp_m = wid & 1;
    int warp_n = wid >> 1;
    int r = lane >> 2;
    int c = lane & 3;
    int sub = lane >> 3;
    int rin = lane & 7;
    int n0 = blockIdx.x * 128;
    int m0 = blockIdx.y * 128;

    uint32_t sbase = (uint32_t)__cvta_generic_to_shared(smh);

    const __half* Wt;
    const float* bias;
    const __half* Ain;
    int zsel = 0;
    if (MODE == 0) {
        zsel = blockIdx.z;
        Wt = g_wth + (size_t)zsel * DD * DD;
        bias = (zsel == 0) ? b0 : (zsel == 1) ? b1 : b2;
        Ain = g_xh;
    } else {
        Wt = g_wth + (size_t)3 * DD * DD;
        bias = b0;
        Ain = g_oh;
    }

    auto load_stage = [&](int st, int kt) {
#pragma unroll
        for (int i = 0; i < 4; i++) {
            int idx = tid + i * 256;
            int row = idx >> 3;
            int ch = idx & 7;
            int swu = ch ^ (row & 7);
            cpasync16(&smh[st * TILE_H + row * 64 + swu * 8],
                      Ain + (size_t)(m0 + row) * DD + kt + ch * 8);
            cpasync16(&smh[(3 + st) * TILE_H + row * 64 + swu * 8],
                      Wt + (size_t)(n0 + row) * DD + kt + ch * 8);
        }
        CP_COMMIT();
    };

    uint32_t a_rb[4], a_r7[4];
#pragma unroll
    for (int mt = 0; mt < 4; mt++) {
        int row = warp_m * 64 + mt * 16 + (sub & 1) * 8 + rin;
        a_rb[mt] = (uint32_t)row * 128;
        a_r7[mt] = (uint32_t)(row & 7);
    }
    int a_usub = sub >> 1;
    uint32_t b_rb[2], b_r7[2];
#pragma unroll
    for (int j = 0; j < 2; j++) {
        int row = warp_n * 32 + (2 * j + (sub >> 1)) * 8 + rin;
        b_rb[j] = (uint32_t)row * 128;
        b_r7[j] = (uint32_t)(row & 7);
    }
    int b_usub = sub & 1;

    float acc[4][4][4];
#pragma unroll
    for (int mt = 0; mt < 4; mt++)
#pragma unroll
        for (int nt = 0; nt < 4; nt++)
#pragma unroll
            for (int i = 0; i < 4; i++) acc[mt][nt][i] = 0.f;

    const int NIT = DD / BKH;   // 16
    load_stage(0, 0);
    load_stage(1, BKH);

    for (int it = 0; it < NIT; it++) {
        if (it + 1 < NIT) { CP_WAIT1(); } else { CP_WAIT0(); }
        __syncthreads();

        if (it + 2 < NIT)
            load_stage((it + 2) % 3, (it + 2) * BKH);

        int st = it % 3;
        uint32_t aB = sbase + st * (TILE_H * 2);
        uint32_t bB = sbase + (3 + st) * (TILE_H * 2);
#pragma unroll
        for (int ks = 0; ks < 4; ks++) {
            uint32_t af[4][4], bf[4][2];
#pragma unroll
            for (int mt = 0; mt < 4; mt++) {
                uint32_t u = (uint32_t)(2 * ks + a_usub) ^ a_r7[mt];
                ldsm_x4(af[mt], aB + a_rb[mt] + (u << 4));
            }
#pragma unroll
            for (int j = 0; j < 2; j++) {
                uint32_t u = (uint32_t)(2 * ks + b_usub) ^ b_r7[j];
                uint32_t t4[4];
                ldsm_x4(t4, bB + b_rb[j] + (u << 4));
                bf[2 * j][0] = t4[0]; bf[2 * j][1] = t4[1];
                bf[2 * j + 1][0] = t4[2]; bf[2 * j + 1][1] = t4[3];
            }
#pragma unroll
            for (int mt = 0; mt < 4; mt++)
#pragma unroll
                for (int nt = 0; nt < 4; nt++)
                    mma_f16(acc[mt][nt], af[mt], bf[nt]);
        }
    }

#pragma unroll
    for (int nt = 0; nt < 4; nt++) {
        int col = n0 + warp_n * 32 + nt * 8 + c * 2;
        float bx = __ldg(&bias[col]);
        float by = __ldg(&bias[col + 1]);
#pragma unroll
        for (int mt = 0; mt < 4; mt++) {
            int row0 = m0 + warp_m * 64 + mt * 16 + r;
            if (MODE == 0) {
                float e0 = acc[mt][nt][0] + bx;
                float e1 = acc[mt][nt][1] + by;
                float e2 = acc[mt][nt][2] + bx;
                float e3 = acc[mt][nt][3] + by;
                if (zsel == 0) {
                    e0 *= QSCALE; e1 *= QSCALE; e2 *= QSCALE; e3 *= QSCALE;
                }
                __half2 h0 = __floats2half2_rn(e0, e1);
                __half2 h1 = __floats2half2_rn(e2, e3);
                int head = col >> 6;
                int d = col & 63;
                int b = row0 >> 11;
                int t = row0 & 2047;
                if (zsel == 2) {
                    __half* vt = g_vth + (((size_t)b * HH + head) * HD) * TT;
                    vt[(size_t)d * TT + t]           = __low2half(h0);
                    vt[(size_t)(d + 1) * TT + t]     = __high2half(h0);
                    vt[(size_t)d * TT + t + 8]       = __low2half(h1);
                    vt[(size_t)(d + 1) * TT + t + 8] = __high2half(h1);
                } else {
                    __half* out = (zsel == 0) ? g_qh : g_kh;
                    size_t base = (((size_t)b * HH + head) * TT + t) * HD + d;
                    *(__half2*)&out[base] = h0;
                    *(__half2*)&out[base + 8 * HD] = h1;
                }
            } else {
                float2 v0, v1;
                v0.x = acc[mt][nt][0] + bx;
                v0.y = acc[mt][nt][1] + by;
                v1.x = acc[mt][nt][2] + bx;
                v1.y = acc[mt][nt][3] + by;
                *(float2*)&OutDirect[(size_t)row0 * DD + col] = v0;
                *(float2*)&OutDirect[(size_t)(row0 + 8) * DD + col] = v1;
            }
        }
    }
}

// ---------------------------------------------------------------------------
// fp16 flash attention; output written directly to g_oh [B*T, D].
// Diagonal supertile: warps whose rows are entirely above the masked band
// skip the fully-masked second half (warp-uniform condition).
// ---------------------------------------------------------------------------
#define HSTR 72
#define VSTR 136

__global__ __launch_bounds__(256, 2) void attn_fa()
{
    extern __shared__ __half sa[];

    int bh = blockIdx.y;
    int qt = gridDim.x - 1 - blockIdx.x;   // LPT
    int m0 = qt * 128;
    int tid = threadIdx.x;
    int wid = tid >> 5;
    int lane = tid & 31;
    int r = lane >> 2;
    int c = lane & 3;
    int sub = lane >> 3;
    int rin = lane & 7;

    uint32_t sbase = (uint32_t)__cvta_generic_to_shared(sa);

    const __half* Qb  = g_qh + (size_t)bh * TT * HD;
    const __half* Kb  = g_kh + (size_t)bh * TT * HD;
    const __half* Vtb = g_vth + (size_t)bh * HD * TT;
    int bI = bh >> 4;
    int head = bh & 15;
    __half* Oout = g_oh + (size_t)bI * TT * DD + head * HD;

    const int NTS = qt + 1;

#pragma unroll
    for (int i = 0; i < 4; i++) {
        int idx = tid + i * 256;
        int krow = idx >> 3;
        int kch = idx & 7;
        cpasync16(&sa[9216 + krow * HSTR + kch * 8],
                  Kb + (size_t)krow * HD + kch * 8);
        int vrow = idx >> 4;
        int vch = idx & 15;
        cpasync16(&sa[27648 + vrow * VSTR + vch * 8],
                  Vtb + (size_t)vrow * TT + vch * 8);
    }
    CP_COMMIT();

#pragma unroll
    for (int i = 0; i < 4; i++) {
        int idx = tid + i * 256;
        int row = idx >> 3;
        int ch = idx & 7;
        *(uint4*)&sa[row * HSTR + ch * 8] =
            *(const uint4*)&Qb[(size_t)(m0 + row) * HD + ch * 8];
    }
    __syncthreads();

    int lr = wid * 16 + r;
    int q_off = (wid * 16 + (sub & 1) * 8 + rin) * HSTR + (sub >> 1) * 8;
    int k_off[4], v_off[4];
#pragma unroll
    for (int j = 0; j < 4; j++) {
        k_off[j] = ((2 * j + (sub >> 1)) * 8 + rin) * HSTR + (sub & 1) * 8;
        v_off[j] = ((2 * j + (sub >> 1)) * 8 + rin) * VSTR + (sub & 1) * 8;
    }

    uint32_t qf[4][4];
#pragma unroll
    for (int kc = 0; kc < 4; kc++)
        ldsm_x4(qf[kc], sbase + (q_off + kc * 16) * 2);

    float o[8][4];
#pragma unroll
    for (int nt = 0; nt < 8; nt++)
#pragma unroll
        for (int i = 0; i < 4; i++) o[nt][i] = 0.f;

    float mr0 = -INFINITY, mr1 = -INFINITY;
    float l0 = 0.f, l1 = 0.f;
    int rg0 = m0 + lr;
    int rg1 = rg0 + 8;
    int wmax = m0 + wid * 16 + 16;    // first key index fully above this warp

    for (int s = 0; s < NTS; s++) {
        CP_WAIT0();
        __syncthreads();

        if (s + 1 < NTS) {
            int kt2 = (s + 1) * 128;
            int st2 = (s + 1) & 1;
#pragma unroll
            for (int i = 0; i < 4; i++) {
                int idx = tid + i * 256;
                int krow = idx >> 3;
                int kch = idx & 7;
                cpasync16(&sa[9216 + st2 * 9216 + krow * HSTR + kch * 8],
                          Kb + (size_t)(kt2 + krow) * HD + kch * 8);
                int vrow = idx >> 4;
                int vch = idx & 15;
                cpasync16(&sa[27648 + st2 * 8704 + vrow * VSTR + vch * 8],
                          Vtb + (size_t)vrow * TT + kt2 + vch * 8);
            }
            CP_COMMIT();
        }

        uint32_t kBase = sbase + (9216 + (s & 1) * 9216) * 2;
        uint32_t vBase = sbase + (27648 + (s & 1) * 8704) * 2;

#pragma unroll
        for (int h = 0; h < 2; h++) {
            int kth = s * 128 + h * 64;
            if (kth >= wmax) continue;   // fully masked for this warp (uniform)
            uint32_t kB = kBase + (h * 64 * HSTR) * 2;
            uint32_t vB = vBase + (h * 64) * 2;

            float sc[8][4];
#pragma unroll
            for (int nt = 0; nt < 8; nt++)
#pragma unroll
                for (int i = 0; i < 4; i++) sc[nt][i] = 0.f;
#pragma unroll
            for (int kc = 0; kc < 4; kc++) {
#pragma unroll
                for (int j = 0; j < 4; j++) {
                    uint32_t t4[4];
                    ldsm_x4(t4, kB + (k_off[j] + kc * 16) * 2);
                    mma_f16(sc[2 * j],     qf[kc], t4);
                    mma_f16(sc[2 * j + 1], qf[kc], t4 + 2);
                }
            }

            bool need_mask = (kth + 63 > m0);
            float mx0 = mr0, mx1 = mr1;
#pragma unroll
            for (int nt = 0; nt < 8; nt++) {
                float* sv = sc[nt];
                if (need_mask) {
                    int col0 = kth + nt * 8 + 2 * c;
                    if (col0     > rg0) sv[0] = -INFINITY;
                    if (col0 + 1 > rg0) sv[1] = -INFINITY;
                    if (col0     > rg1) sv[2] = -INFINITY;
                    if (col0 + 1 > rg1) sv[3] = -INFINITY;
                }
                mx0 = fmaxf(mx0, fmaxf(sv[0], sv[1]));
                mx1 = fmaxf(mx1, fmaxf(sv[2], sv[3]));
            }
            mx0 = fmaxf(mx0, __shfl_xor_sync(0xffffffffu, mx0, 1));
            mx0 = fmaxf(mx0, __shfl_xor_sync(0xffffffffu, mx0, 2));
            mx1 = fmaxf(mx1, __shfl_xor_sync(0xffffffffu, mx1, 1));
            mx1 = fmaxf(mx1, __shfl_xor_sync(0xffffffffu, mx1, 2));

            float a0 = ex2(mr0 - mx0);
            float a1 = ex2(mr1 - mx1);
            float sum0 = 0.f, sum1 = 0.f;
            uint32_t pk[8][2];
#pragma unroll
            for (int nt = 0; nt < 8; nt++) {
                __half2 d01 = __floats2half2_rn(sc[nt][0] - mx0,
                                                sc[nt][1] - mx0);
                __half2 d23 = __floats2half2_rn(sc[nt][2] - mx1,
                                                sc[nt][3] - mx1);
                pk[nt][0] = ex2_h2(*(uint32_t*)&d01);
                pk[nt][1] = ex2_h2(*(uint32_t*)&d23);
                float2 f01 = __half22float2(*(__half2*)&pk[nt][0]);
                float2 f23 = __half22float2(*(__half2*)&pk[nt][1]);
                sum0 += f01.x + f01.y;
                sum1 += f23.x + f23.y;
            }
            sum0 += __shfl_xor_sync(0xffffffffu, sum0, 1);
            sum0 += __shfl_xor_sync(0xffffffffu, sum0, 2);
            sum1 += __shfl_xor_sync(0xffffffffu, sum1, 1);
            sum1 += __shfl_xor_sync(0xffffffffu, sum1, 2);
            l0 = l0 * a0 + sum0;
            l1 = l1 * a1 + sum1;
#pragma unroll
            for (int nt = 0; nt < 8; nt++) {
                o[nt][0] *= a0; o[nt][1] *= a0;
                o[nt][2] *= a1; o[nt][3] *= a1;
            }
            mr0 = mx0; mr1 = mx1;

#pragma unroll
            for (int kc = 0; kc < 4; kc++) {
                uint32_t af[4];
                af[0] = pk[2 * kc][0];
                af[1] = pk[2 * kc][1];
                af[2] = pk[2 * kc + 1][0];
                af[3] = pk[2 * kc + 1][1];
#pragma unroll
                for (int j = 0; j < 4; j++) {
                    uint32_t t4[4];
                    ldsm_x4(t4, vB + (v_off[j] + kc * 16) * 2);
                    mma_f16(o[2 * j],     af, t4);
                    mma_f16(o[2 * j + 1], af, t4 + 2);
                }
            }
        }
    }

    // ---- output directly into [B*T, D] fp16 ----
    float i0 = 1.f / l0, i1 = 1.f / l1;
#pragma unroll
    for (int nt = 0; nt < 8; nt++) {
        *(__half2*)&Oout[(size_t)rg0 * DD + nt * 8 + 2 * c] =
            __floats2half2_rn(o[nt][0] * i0, o[nt][1] * i0);
        *(__half2*)&Oout[(size_t)rg1 * DD + nt * 8 + 2 * c] =
            __floats2half2_rn(o[nt][2] * i1, o[nt][3] * i1);
    }
}

extern "C" void kernel_launch(void* const* d_in, const int* in_sizes, int n_in,
                              void* d_out, int out_size)
{
    const float* x  = (const float*)d_in[0];
    const float* Wq = (const float*)d_in[1];
    const float* bq = (const float*)d_in[2];
    const float* Wk = (const float*)d_in[3];
    const float* bk = (const float*)d_in[4];
    const float* Wv = (const float*)d_in[5];
    const float* bv = (const float*)d_in[6];
    const float* Wo = (const float*)d_in[7];
    const float* bo = (const float*)d_in[8];
    float* out = (float*)d_out;

    const int GEMM_SMEM = 6 * TILE_H * 2;   // 98304 B
    const int ATTN_SMEM = 45056 * 2;        // 90112 B
    cudaFuncSetAttribute(gemm_tc<0>, cudaFuncAttributeMaxDynamicSharedMemorySize,
                         GEMM_SMEM);
    cudaFuncSetAttribute(gemm_tc<1>, cudaFuncAttributeMaxDynamicSharedMemorySize,
                         GEMM_SMEM);
    cudaFuncSetAttribute(attn_fa, cudaFuncAttributeMaxDynamicSharedMemorySize,
                         ATTN_SMEM);

    prep<<<8192 + 4096, 256>>>(x, Wq, Wk, Wv, Wo);

    dim3 g1(DD / 128, (BB * TT) / 128, 3);
    gemm_tc<0><<<g1, 256, GEMM_SMEM>>>(bq, bk, bv, nullptr);

    dim3 g2(TT / 128, BB * HH);
    attn_fa<<<g2, 256, ATTN_SMEM>>>();

    dim3 g3(DD / 128, (BB * TT) / 128);
    gemm_tc<1><<<g3, 256, GEMM_SMEM>>>(bo, nullptr, nullptr, out);
}